// round 1
// baseline (speedup 1.0000x reference)
#include <cuda_runtime.h>

// ---------------------------------------------------------------------------
// NATTEN cross-attention block, fp32 baseline.
// Pipeline: conv3x3(q) -> rmsnorm+qproj -> rmsnorm+kproj(k) -> attention
// Attention insight: upsample-by-4 + dilation-4 NATTEN == each 4x4 query block
// attends to a 7x7 window of the ORIGINAL 32x32 k/v grid, window start
// clamp(iq-3, 0, 25).
// ---------------------------------------------------------------------------

#define EPSF 1.1920928955078125e-7f

__device__ float g_qc[128 * 128 * 128];   // conv output, NCHW
__device__ float g_qf[128 * 128 * 128];   // q final, pixel-major [y*128+x][c]
__device__ float g_kf[32 * 32 * 128];     // k final, pixel-major [y*32+x][c]
__device__ float g_vt[32 * 32 * 128];     // v transposed, pixel-major
__device__ float g_Wq[128 * 128];         // qproj_w * normq_w[c]
__device__ float g_Wk[128 * 128];         // kproj_w * normk_w[c]

// ---------------------------------------------------------------------------
__global__ void fold_kernel(const float* __restrict__ qw, const float* __restrict__ nq,
                            const float* __restrict__ kw, const float* __restrict__ nk) {
    int i = blockIdx.x * 256 + threadIdx.x;
    if (i < 128 * 128) {
        int c = i & 127;
        g_Wq[i] = qw[i] * nq[c];
        g_Wk[i] = kw[i] * nk[c];
    }
}

// ---------------------------------------------------------------------------
// v transpose: NCHW [c][y][x] (32x32) -> pixel-major [y*32+x][c]
__global__ void vtrans_kernel(const float* __restrict__ v) {
    int i = blockIdx.x * 256 + threadIdx.x;
    if (i < 32 * 32 * 128) {
        int c = i >> 10;
        int p = i & 1023;
        g_vt[p * 128 + c] = v[i];
    }
}

// ---------------------------------------------------------------------------
// Direct 3x3 conv, SAME zero padding, 128->128 channels over 128x128.
// CTA: 16 output channels x 16x16 spatial tile. 256 threads, 1 pixel each,
// 16 accumulators. Weights staged in smem [icl][k][16oc] for broadcast float4.
__global__ void conv3_kernel(const float* __restrict__ x, const float* __restrict__ w) {
    __shared__ float sIn[4][18][18];
    __shared__ float sW[4][9][16];
    int ocb = blockIdx.x, by = blockIdx.y, bx = blockIdx.z;
    int tid = threadIdx.x;
    int ty = tid >> 4, tx = tid & 15;
    int gy0 = by * 16 - 1, gx0 = bx * 16 - 1;

    float acc[16];
#pragma unroll
    for (int i = 0; i < 16; i++) acc[i] = 0.f;

    for (int ic0 = 0; ic0 < 128; ic0 += 4) {
        for (int idx = tid; idx < 4 * 324; idx += 256) {
            int icl = idx / 324;
            int r = idx - icl * 324;
            int py = r / 18, px = r - py * 18;
            int gy = gy0 + py, gx = gx0 + px;
            float v = 0.f;
            if (gy >= 0 && gy < 128 && gx >= 0 && gx < 128)
                v = x[(ic0 + icl) * 16384 + gy * 128 + gx];
            sIn[icl][py][px] = v;
        }
        for (int idx = tid; idx < 576; idx += 256) {
            int o = idx & 15;
            int k = (idx >> 4) % 9;
            int icl = idx / 144;
            sW[icl][k][o] = w[((ocb * 16 + o) * 128 + ic0 + icl) * 9 + k];
        }
        __syncthreads();
#pragma unroll
        for (int icl = 0; icl < 4; icl++) {
            float in9[9];
#pragma unroll
            for (int dy = 0; dy < 3; dy++)
#pragma unroll
                for (int dx = 0; dx < 3; dx++)
                    in9[dy * 3 + dx] = sIn[icl][ty + dy][tx + dx];
#pragma unroll
            for (int k = 0; k < 9; k++) {
                const float4* wp = (const float4*)&sW[icl][k][0];
                float4 w0 = wp[0], w1 = wp[1], w2 = wp[2], w3 = wp[3];
                float iv = in9[k];
                acc[0]  += w0.x * iv; acc[1]  += w0.y * iv; acc[2]  += w0.z * iv; acc[3]  += w0.w * iv;
                acc[4]  += w1.x * iv; acc[5]  += w1.y * iv; acc[6]  += w1.z * iv; acc[7]  += w1.w * iv;
                acc[8]  += w2.x * iv; acc[9]  += w2.y * iv; acc[10] += w2.z * iv; acc[11] += w2.w * iv;
                acc[12] += w3.x * iv; acc[13] += w3.y * iv; acc[14] += w3.z * iv; acc[15] += w3.w * iv;
            }
        }
        __syncthreads();
    }
    int y = by * 16 + ty, xx = bx * 16 + tx;
#pragma unroll
    for (int o = 0; o < 16; o++)
        g_qc[(ocb * 16 + o) * 16384 + y * 128 + xx] = acc[o];
}

// ---------------------------------------------------------------------------
// Fused RMSNorm + 1x1 projection.
// out[pix][o] = rsqrt(mean_c x^2 + eps) * sum_c Wf[o][c]*x[c][pix] + b[o]
// (norm weight pre-folded into Wf). CTA: 32 consecutive pixels. 256 threads.
__global__ void proj_kernel(const float* __restrict__ xin, const float* __restrict__ Wf,
                            const float* __restrict__ bias, float* __restrict__ outp,
                            int HW) {
    __shared__ float xs[128 * 33];
    __shared__ float red[8 * 32];
    __shared__ float rs[32];
    __shared__ float ob[32 * 129];
    int tid = threadIdx.x;
    int p0 = blockIdx.x * 32;

    for (int idx = tid; idx < 128 * 32; idx += 256) {
        int c = idx >> 5, px = idx & 31;
        xs[c * 33 + px] = xin[c * HW + p0 + px];
    }
    __syncthreads();
    {
        int px = tid & 31, g = tid >> 5;
        float s = 0.f;
#pragma unroll
        for (int j = 0; j < 16; j++) {
            float v = xs[(g * 16 + j) * 33 + px];
            s += v * v;
        }
        red[g * 32 + px] = s;
    }
    __syncthreads();
    if (tid < 32) {
        float s = 0.f;
#pragma unroll
        for (int g = 0; g < 8; g++) s += red[g * 32 + tid];
        rs[tid] = rsqrtf(s * (1.f / 128.f) + EPSF);
    }
    __syncthreads();
    {
        int px = tid & 31, og = tid >> 5;
        float acc[16];
#pragma unroll
        for (int i = 0; i < 16; i++) acc[i] = 0.f;
        for (int c0 = 0; c0 < 128; c0 += 4) {
            float x0 = xs[(c0 + 0) * 33 + px];
            float x1 = xs[(c0 + 1) * 33 + px];
            float x2 = xs[(c0 + 2) * 33 + px];
            float x3 = xs[(c0 + 3) * 33 + px];
#pragma unroll
            for (int oi = 0; oi < 16; oi++) {
                const float4 wv = __ldg((const float4*)(Wf + (og * 16 + oi) * 128 + c0));
                acc[oi] += wv.x * x0 + wv.y * x1 + wv.z * x2 + wv.w * x3;
            }
        }
        float r = rs[px];
#pragma unroll
        for (int oi = 0; oi < 16; oi++)
            ob[px * 129 + og * 16 + oi] = acc[oi] * r + bias[og * 16 + oi];
    }
    __syncthreads();
    for (int idx = tid; idx < 4096; idx += 256) {
        int px = idx >> 7, c = idx & 127;
        outp[p0 * 128 + idx] = ob[px * 129 + c];
    }
}

// ---------------------------------------------------------------------------
// Attention. 1 CTA per 4x4 query block (grid 1024). Key window = 7x7 of the
// original 32x32 k/v grid at start clamp(iq-3, 0, 25). 128 threads.
__global__ __launch_bounds__(128) void attn_kernel(float* __restrict__ outp) {
    extern __shared__ float sm[];
    float* ks = sm;                 // [49][128]
    float* vs = ks + 49 * 128;      // [49][128]
    float* qs = vs + 49 * 128;      // [16][128]
    float* pr = qs + 16 * 128;      // [16*4][52]
    float* am = pr + 64 * 52;       // [16][52]
    int tid = threadIdx.x;
    int iq = blockIdx.x >> 5, jq = blockIdx.x & 31;
    int sy = iq - 3; sy = sy < 0 ? 0 : (sy > 25 ? 25 : sy);
    int sx = jq - 3; sx = sx < 0 ? 0 : (sx > 25 ? 25 : sx);

    float4* ks4 = (float4*)ks;
    float4* vs4 = (float4*)vs;
    float4* qs4 = (float4*)qs;
    const float4* kf4 = (const float4*)g_kf;
    const float4* vt4 = (const float4*)g_vt;
    const float4* qf4 = (const float4*)g_qf;

    for (int i = tid; i < 49 * 32; i += 128) {
        int kk = i >> 5, c4 = i & 31;
        int m = kk / 7, n = kk - m * 7;
        int pix = (sy + m) * 32 + sx + n;
        ks4[i] = kf4[pix * 32 + c4];
        vs4[i] = vt4[pix * 32 + c4];
    }
    for (int i = tid; i < 16 * 32; i += 128) {
        int ql = i >> 5, c4 = i & 31;
        int y = iq * 4 + (ql >> 2), xx = jq * 4 + (ql & 3);
        qs4[i] = qf4[(y * 128 + xx) * 32 + c4];
    }
    __syncthreads();

    // Phase 1: logits + softmax per (query, head). 64 threads, one (q,h) each.
    if (tid < 64) {
        int q = tid & 15, h = tid >> 4;
        float4 qr[8];
        const float4* qp = (const float4*)(qs + q * 128 + h * 32);
#pragma unroll
        for (int j = 0; j < 8; j++) qr[j] = qp[j];
        float l[49];
        float mx = -1e30f;
#pragma unroll
        for (int kk = 0; kk < 49; kk++) {
            const float4* kp = (const float4*)(ks + kk * 128 + h * 32);
            float s = 0.f;
#pragma unroll
            for (int j = 0; j < 8; j++) {
                float4 kv = kp[j];
                s += qr[j].x * kv.x + qr[j].y * kv.y + qr[j].z * kv.z + qr[j].w * kv.w;
            }
            s *= 0.17677669529663687f;   // 32^-0.5
            l[kk] = s;
            mx = fmaxf(mx, s);
        }
        float sum = 0.f;
#pragma unroll
        for (int kk = 0; kk < 49; kk++) {
            float e = __expf(l[kk] - mx);
            l[kk] = e;
            sum += e;
        }
        float inv = 1.f / sum;
        float* prow = pr + (q * 4 + h) * 52;
#pragma unroll
        for (int kk = 0; kk < 49; kk++) prow[kk] = l[kk] * inv;
    }
    __syncthreads();

    // Head mean (deterministic, no atomics)
    for (int i = tid; i < 16 * 49; i += 128) {
        int q = i / 49, kk = i - q * 49;
        am[q * 52 + kk] = 0.25f * (pr[(q * 4 + 0) * 52 + kk] + pr[(q * 4 + 1) * 52 + kk] +
                                   pr[(q * 4 + 2) * 52 + kk] + pr[(q * 4 + 3) * 52 + kk]);
    }
    __syncthreads();

    // Phase 2: V contraction. Thread owns (qy, cbase); emits float4 over qx.
    {
        int qy = tid & 3, cb = tid >> 2;
        const float* a0 = am + (qy * 4 + 0) * 52;
        const float* a1 = am + (qy * 4 + 1) * 52;
        const float* a2 = am + (qy * 4 + 2) * 52;
        const float* a3 = am + (qy * 4 + 3) * 52;
        float4* out4 = (float4*)outp;
#pragma unroll
        for (int j = 0; j < 4; j++) {
            int c = cb + 32 * j;
            float r0 = 0.f, r1 = 0.f, r2 = 0.f, r3 = 0.f;
#pragma unroll
            for (int kk = 0; kk < 49; kk++) {
                float v = vs[kk * 128 + c];
                r0 += a0[kk] * v;
                r1 += a1[kk] * v;
                r2 += a2[kk] * v;
                r3 += a3[kk] * v;
            }
            out4[(c * 128 + iq * 4 + qy) * 32 + jq] = make_float4(r0, r1, r2, r3);
        }
    }
}

// ---------------------------------------------------------------------------
extern "C" void kernel_launch(void* const* d_in, const int* in_sizes, int n_in,
                              void* d_out, int out_size) {
    (void)in_sizes; (void)n_in; (void)out_size;
    const float* q  = (const float*)d_in[0];
    const float* k  = (const float*)d_in[1];
    const float* v  = (const float*)d_in[2];
    const float* cw = (const float*)d_in[3];
    const float* nq = (const float*)d_in[4];
    const float* nk = (const float*)d_in[5];
    const float* qw = (const float*)d_in[6];
    const float* qb = (const float*)d_in[7];
    const float* kw = (const float*)d_in[8];
    const float* kb = (const float*)d_in[9];
    float* out = (float*)d_out;

    void *qc_p, *qf_p, *kf_p, *wq_p, *wk_p;
    cudaGetSymbolAddress(&qc_p, g_qc);
    cudaGetSymbolAddress(&qf_p, g_qf);
    cudaGetSymbolAddress(&kf_p, g_kf);
    cudaGetSymbolAddress(&wq_p, g_Wq);
    cudaGetSymbolAddress(&wk_p, g_Wk);

    fold_kernel<<<64, 256>>>(qw, nq, kw, nk);
    vtrans_kernel<<<512, 256>>>(v);
    conv3_kernel<<<dim3(8, 8, 8), 256>>>(q, cw);
    proj_kernel<<<512, 256>>>((const float*)qc_p, (const float*)wq_p, qb, (float*)qf_p, 16384);
    proj_kernel<<<32, 256>>>(k, (const float*)wk_p, kb, (float*)kf_p, 1024);

    const int attn_smem = (49 * 128 * 2 + 16 * 128 + 64 * 52 + 16 * 52) * 4;  // 75008 B
    cudaFuncSetAttribute(attn_kernel, cudaFuncAttributeMaxDynamicSharedMemorySize, attn_smem);
    attn_kernel<<<1024, 128, attn_smem>>>(out);
}

// round 2
// speedup vs baseline: 1.0958x; 1.0958x over previous
#include <cuda_runtime.h>

// ---------------------------------------------------------------------------
// NATTEN cross-attention block, fp32 + packed FFMA2 (fma.rn.f32x2).
// Pipeline: conv3x3(q) -> rmsnorm+qproj -> rmsnorm+kproj(k) -> attention
// Attention: upsample-by-4 + dilation-4 NATTEN == each 4x4 query block attends
// to a 7x7 window of the ORIGINAL 32x32 k/v grid, start clamp(iq-3, 0, 25).
// ---------------------------------------------------------------------------

#define EPSF 1.1920928955078125e-7f
typedef unsigned long long ull;

__device__ float g_qc[128 * 128 * 128];   // conv output, NCHW
__device__ float g_qf[128 * 128 * 128];   // q final, pixel-major [pix][c]
__device__ float g_kf[32 * 32 * 128];     // k final, pixel-major
__device__ float g_vt[32 * 32 * 128];     // v transposed, pixel-major
__device__ float g_Wq[128 * 128];         // TRANSPOSED folded qproj: [c][o]
__device__ float g_Wk[128 * 128];         // TRANSPOSED folded kproj: [c][o]

__device__ __forceinline__ ull pack2(float v) {
    ull r; asm("mov.b64 %0, {%1, %1};" : "=l"(r) : "f"(v)); return r;
}
__device__ __forceinline__ void ffma2(ull& d, ull a, ull b) {
    asm("fma.rn.f32x2 %0, %1, %2, %0;" : "+l"(d) : "l"(a), "l"(b));
}
__device__ __forceinline__ float2 unpack2(ull v) {
    float2 f; asm("mov.b64 {%0, %1}, %2;" : "=f"(f.x), "=f"(f.y) : "l"(v)); return f;
}

// ---------------------------------------------------------------------------
// Fold norm weights into 1x1 proj weights, store TRANSPOSED [c][o].
__global__ void fold_kernel(const float* __restrict__ qw, const float* __restrict__ nq,
                            const float* __restrict__ kw, const float* __restrict__ nk) {
    int i = blockIdx.x * 256 + threadIdx.x;   // i = c*128 + o
    if (i < 128 * 128) {
        int c = i >> 7, o = i & 127;
        g_Wq[i] = qw[o * 128 + c] * nq[c];
        g_Wk[i] = kw[o * 128 + c] * nk[c];
    }
}

// v transpose: NCHW [c][1024] -> pixel-major [pix][c]
__global__ void vtrans_kernel(const float* __restrict__ v) {
    int i = blockIdx.x * 256 + threadIdx.x;
    if (i < 32 * 32 * 128) {
        int c = i >> 10, p = i & 1023;
        g_vt[p * 128 + c] = v[i];
    }
}

// ---------------------------------------------------------------------------
// Direct 3x3 conv, SAME padding, 128->128 ch over 128x128, packed f32x2.
// CTA: 16 oc x 16x16 pixels, 256 threads, 8 packed oc-pair accumulators.
__global__ __launch_bounds__(256) void conv3_kernel(const float* __restrict__ x,
                                                    const float* __restrict__ w) {
    __shared__ __align__(16) float sIn[8][18][18];
    __shared__ __align__(16) float sW[8][9][16];
    int ocb = blockIdx.x, by = blockIdx.y, bx = blockIdx.z;
    int tid = threadIdx.x;
    int ty = tid >> 4, tx = tid & 15;
    int gy0 = by * 16 - 1, gx0 = bx * 16 - 1;

    ull acc2[8];
#pragma unroll
    for (int i = 0; i < 8; i++) acc2[i] = 0ULL;

    for (int ic0 = 0; ic0 < 128; ic0 += 8) {
        for (int idx = tid; idx < 8 * 324; idx += 256) {
            int icl = idx / 324;
            int r = idx - icl * 324;
            int py = r / 18, px = r - py * 18;
            int gy = gy0 + py, gx = gx0 + px;
            float v = 0.f;
            if (gy >= 0 && gy < 128 && gx >= 0 && gx < 128)
                v = x[(ic0 + icl) * 16384 + gy * 128 + gx];
            sIn[icl][py][px] = v;
        }
        for (int idx = tid; idx < 1152; idx += 256) {
            int o = idx & 15;
            int k = (idx >> 4) % 9;
            int icl = idx / 144;
            sW[icl][k][o] = w[((ocb * 16 + o) * 128 + ic0 + icl) * 9 + k];
        }
        __syncthreads();
#pragma unroll
        for (int icl = 0; icl < 8; icl++) {
            ull iv2[9];
#pragma unroll
            for (int dy = 0; dy < 3; dy++)
#pragma unroll
                for (int dx = 0; dx < 3; dx++)
                    iv2[dy * 3 + dx] = pack2(sIn[icl][ty + dy][tx + dx]);
#pragma unroll
            for (int k = 0; k < 9; k++) {
                const ulonglong2* wp = (const ulonglong2*)&sW[icl][k][0];
                ulonglong2 wa = wp[0], wb = wp[1], wc = wp[2], wd = wp[3];
                ull iv = iv2[k];
                ffma2(acc2[0], wa.x, iv); ffma2(acc2[1], wa.y, iv);
                ffma2(acc2[2], wb.x, iv); ffma2(acc2[3], wb.y, iv);
                ffma2(acc2[4], wc.x, iv); ffma2(acc2[5], wc.y, iv);
                ffma2(acc2[6], wd.x, iv); ffma2(acc2[7], wd.y, iv);
            }
        }
        __syncthreads();
    }
    int y = by * 16 + ty, xx = bx * 16 + tx;
#pragma unroll
    for (int i = 0; i < 8; i++) {
        float2 f = unpack2(acc2[i]);
        g_qc[(ocb * 16 + 2 * i) * 16384 + y * 128 + xx] = f.x;
        g_qc[(ocb * 16 + 2 * i + 1) * 16384 + y * 128 + xx] = f.y;
    }
}

// ---------------------------------------------------------------------------
// Fused RMSNorm + 1x1 projection, register-blocked f32x2 GEMM.
// CTA: 128 pixels x 128 oc, 256 threads, thread = 8 px x 8 oc.
// Wt is [c][o] so weight pairs stream naturally packed. Norm scale in epilogue.
__global__ __launch_bounds__(256) void proj_kernel(const float* __restrict__ xin,
                                                   const float* __restrict__ Wt,
                                                   const float* __restrict__ bias,
                                                   float* __restrict__ outp, int HW) {
    __shared__ __align__(16) float xs[128 * 128];   // [c][px]
    __shared__ float red[2][128];
    __shared__ float rs[128];
    int tid = threadIdx.x;
    int p0 = blockIdx.x * 128;

    float4* xs4 = (float4*)xs;
    const float4* xin4 = (const float4*)xin;
    for (int idx = tid; idx < 4096; idx += 256) {
        int c = idx >> 5, seg = idx & 31;
        xs4[idx] = xin4[c * (HW >> 2) + (p0 >> 2) + seg];
    }
    __syncthreads();
    {
        int px = tid & 127, half = tid >> 7;
        float s = 0.f;
#pragma unroll
        for (int j = 0; j < 64; j++) {
            float v = xs[(half * 64 + j) * 128 + px];
            s += v * v;
        }
        red[half][px] = s;
    }
    __syncthreads();
    if (tid < 128) rs[tid] = rsqrtf((red[0][tid] + red[1][tid]) * (1.f / 128.f) + EPSF);
    __syncthreads();

    int pxb = (tid & 15) * 8;
    int ocb = (tid >> 4) * 8;
    ull acc[8][4];
#pragma unroll
    for (int i = 0; i < 8; i++)
#pragma unroll
        for (int j = 0; j < 4; j++) acc[i][j] = 0ULL;

    for (int c = 0; c < 128; c++) {
        float4 xa = xs4[c * 32 + (pxb >> 2)];
        float4 xb = xs4[c * 32 + (pxb >> 2) + 1];
        ull xd[8];
        xd[0] = pack2(xa.x); xd[1] = pack2(xa.y); xd[2] = pack2(xa.z); xd[3] = pack2(xa.w);
        xd[4] = pack2(xb.x); xd[5] = pack2(xb.y); xd[6] = pack2(xb.z); xd[7] = pack2(xb.w);
        const ulonglong2* wp = (const ulonglong2*)(Wt + c * 128 + ocb);
        ulonglong2 w0 = wp[0], w1 = wp[1];
#pragma unroll
        for (int px = 0; px < 8; px++) {
            ffma2(acc[px][0], w0.x, xd[px]);
            ffma2(acc[px][1], w0.y, xd[px]);
            ffma2(acc[px][2], w1.x, xd[px]);
            ffma2(acc[px][3], w1.y, xd[px]);
        }
    }
    float4 bA = __ldg((const float4*)(bias + ocb));
    float4 bB = __ldg((const float4*)(bias + ocb + 4));
#pragma unroll
    for (int px = 0; px < 8; px++) {
        float r = rs[pxb + px];
        float2 f0 = unpack2(acc[px][0]), f1 = unpack2(acc[px][1]);
        float2 f2 = unpack2(acc[px][2]), f3 = unpack2(acc[px][3]);
        float4 oA = make_float4(f0.x * r + bA.x, f0.y * r + bA.y, f1.x * r + bA.z, f1.y * r + bA.w);
        float4 oB = make_float4(f2.x * r + bB.x, f2.y * r + bB.y, f3.x * r + bB.z, f3.y * r + bB.w);
        float4* op = (float4*)(outp + (p0 + pxb + px) * 128 + ocb);
        op[0] = oA; op[1] = oB;
    }
}

// ---------------------------------------------------------------------------
// Attention. 1 CTA per 4x4 query block (grid 1024), 128 threads.
// smem floats: ks[49][132] vs[49][128] qs[16][132] pr[64][50] amT[49][16]
__global__ __launch_bounds__(128) void attn_kernel(float* __restrict__ outp) {
    extern __shared__ __align__(16) float sm[];
    float* ks = sm;                  // stride 132 (conflict-free across kk)
    float* vs = ks + 49 * 132;       // stride 128
    float* qs = vs + 49 * 128;       // stride 132
    float* pr = qs + 16 * 132;       // [64][50]
    float* amT = pr + 64 * 50;       // [49][16]
    int tid = threadIdx.x;
    int iq = blockIdx.x >> 5, jq = blockIdx.x & 31;
    int sy = iq - 3; sy = sy < 0 ? 0 : (sy > 25 ? 25 : sy);
    int sx = jq - 3; sx = sx < 0 ? 0 : (sx > 25 ? 25 : sx);

    {
        float4* ks4 = (float4*)ks;
        float4* vs4 = (float4*)vs;
        float4* qs4 = (float4*)qs;
        const float4* kf4 = (const float4*)g_kf;
        const float4* vt4 = (const float4*)g_vt;
        const float4* qf4 = (const float4*)g_qf;
        for (int i = tid; i < 49 * 32; i += 128) {
            int kk = i >> 5, c4 = i & 31;
            int m = kk / 7, n = kk - m * 7;
            int pix = (sy + m) * 32 + sx + n;
            ks4[kk * 33 + c4] = kf4[pix * 32 + c4];
            vs4[kk * 32 + c4] = vt4[pix * 32 + c4];
        }
        for (int i = tid; i < 16 * 32; i += 128) {
            int ql = i >> 5, c4 = i & 31;
            int y = iq * 4 + (ql >> 2), xx = jq * 4 + (ql & 3);
            qs4[ql * 33 + c4] = qf4[(y * 128 + xx) * 32 + c4];
        }
    }
    __syncthreads();

    // Phase 1: logits + softmax. warp = head; thread = (q, s) with s the
    // key-half; pair lanes (s=0,1) are adjacent -> shfl.bfly reduction.
    {
        int h = tid >> 5, qi = (tid >> 1) & 15, s = tid & 1;
        const ulonglong2* qp = (const ulonglong2*)(qs + qi * 132 + h * 32);
        ull qr[16];
#pragma unroll
        for (int j = 0; j < 8; j++) { ulonglong2 v = qp[j]; qr[2 * j] = v.x; qr[2 * j + 1] = v.y; }
        int k0 = s * 24;            // s=0: keys 0..24, s=1: keys 24..48 (24 dup-skipped)
        float l[25];
        float mx = -1e30f;
#pragma unroll
        for (int kk = 0; kk < 25; kk++) {
            const ulonglong2* kp = (const ulonglong2*)(ks + (k0 + kk) * 132 + h * 32);
            ull a = 0ULL;
#pragma unroll
            for (int j = 0; j < 8; j++) {
                ulonglong2 kv = kp[j];
                ffma2(a, qr[2 * j], kv.x);
                ffma2(a, qr[2 * j + 1], kv.y);
            }
            float2 f = unpack2(a);
            float sc = (f.x + f.y) * 0.17677669529663687f;   // 32^-0.5
            l[kk] = sc;
            mx = fmaxf(mx, sc);
        }
        mx = fmaxf(mx, __shfl_xor_sync(0xffffffffu, mx, 1));
        float sum = 0.f;
#pragma unroll
        for (int kk = 0; kk < 25; kk++) {
            if (s && kk == 0) continue;   // skip duplicated key 24 on lane s=1
            float e = __expf(l[kk] - mx);
            l[kk] = e;
            sum += e;
        }
        sum += __shfl_xor_sync(0xffffffffu, sum, 1);
        float inv = 1.f / sum;
        float* prow = pr + (qi * 4 + h) * 50;
#pragma unroll
        for (int kk = 0; kk < 25; kk++) {
            if (s && kk == 0) continue;
            prow[k0 + kk] = l[kk] * inv;
        }
    }
    __syncthreads();

    // Head mean, transposed: amT[kk][q]
    for (int i = tid; i < 16 * 49; i += 128) {
        int q = i / 49, kk = i - q * 49;
        amT[kk * 16 + q] = 0.25f * (pr[(q * 4 + 0) * 50 + kk] + pr[(q * 4 + 1) * 50 + kk] +
                                    pr[(q * 4 + 2) * 50 + kk] + pr[(q * 4 + 3) * 50 + kk]);
    }
    __syncthreads();

    // Phase 2: V contraction, f32x2 over query-x pairs. warp = qy (out row).
    {
        int qy = tid >> 5, cb = tid & 31;
        ull acc[4][2];
#pragma unroll
        for (int j = 0; j < 4; j++) { acc[j][0] = 0ULL; acc[j][1] = 0ULL; }
#pragma unroll
        for (int kk = 0; kk < 49; kk++) {
            const ull* ap = (const ull*)(amT + kk * 16 + qy * 4);
            ull a01 = ap[0], a23 = ap[1];
#pragma unroll
            for (int j = 0; j < 4; j++) {
                ull vv = pack2(vs[kk * 128 + cb + 32 * j]);
                ffma2(acc[j][0], a01, vv);
                ffma2(acc[j][1], a23, vv);
            }
        }
        int y = iq * 4 + qy;
#pragma unroll
        for (int j = 0; j < 4; j++) {
            int c = cb + 32 * j;
            float2 r01 = unpack2(acc[j][0]);
            float2 r23 = unpack2(acc[j][1]);
            float4* op = (float4*)(outp + c * 16384 + y * 128 + jq * 4);
            op[0] = make_float4(r01.x, r01.y, r23.x, r23.y);
        }
    }
}

// ---------------------------------------------------------------------------
extern "C" void kernel_launch(void* const* d_in, const int* in_sizes, int n_in,
                              void* d_out, int out_size) {
    (void)in_sizes; (void)n_in; (void)out_size;
    const float* q  = (const float*)d_in[0];
    const float* k  = (const float*)d_in[1];
    const float* v  = (const float*)d_in[2];
    const float* cw = (const float*)d_in[3];
    const float* nq = (const float*)d_in[4];
    const float* nk = (const float*)d_in[5];
    const float* qw = (const float*)d_in[6];
    const float* qb = (const float*)d_in[7];
    const float* kw = (const float*)d_in[8];
    const float* kb = (const float*)d_in[9];
    float* out = (float*)d_out;

    void *qc_p, *qf_p, *kf_p, *wq_p, *wk_p;
    cudaGetSymbolAddress(&qc_p, g_qc);
    cudaGetSymbolAddress(&qf_p, g_qf);
    cudaGetSymbolAddress(&kf_p, g_kf);
    cudaGetSymbolAddress(&wq_p, g_Wq);
    cudaGetSymbolAddress(&wk_p, g_Wk);

    fold_kernel<<<64, 256>>>(qw, nq, kw, nk);
    vtrans_kernel<<<512, 256>>>(v);
    conv3_kernel<<<dim3(8, 8, 8), 256>>>(q, cw);
    proj_kernel<<<128, 256>>>((const float*)qc_p, (const float*)wq_p, qb, (float*)qf_p, 16384);
    proj_kernel<<<8, 256>>>(k, (const float*)wk_p, kb, (float*)kf_p, 1024);

    const int attn_smem = (49 * 132 + 49 * 128 + 16 * 132 + 64 * 50 + 49 * 16) * 4;  // 75344 B
    cudaFuncSetAttribute(attn_kernel, cudaFuncAttributeMaxDynamicSharedMemorySize, attn_smem);
    attn_kernel<<<1024, 128, attn_smem>>>(out);
}

// round 3
// speedup vs baseline: 1.1775x; 1.0746x over previous
#include <cuda_runtime.h>

// ---------------------------------------------------------------------------
// NATTEN cross-attention block, fp32 + packed FFMA2, stall-optimized.
// conv3x3(q) -> rmsnorm+qproj -> rmsnorm+kproj(k) -> attention.
// Attention: upsample-by-4 + dilation-4 NATTEN == each 4x4 query block attends
// to a 7x7 window of the ORIGINAL 32x32 k/v grid, start clamp(iq-3, 0, 25).
// ---------------------------------------------------------------------------

#define EPSF 1.1920928955078125e-7f
typedef unsigned long long ull;

__device__ float g_qc[128 * 128 * 128];   // conv output, NCHW
__device__ float g_qf[128 * 128 * 128];   // q final, pixel-major [pix][c]
__device__ float g_kf[32 * 32 * 128];     // k final, pixel-major
__device__ float g_vt[32 * 32 * 128];     // v transposed, pixel-major
__device__ float g_Wq[128 * 128];         // TRANSPOSED folded qproj: [c][o]
__device__ float g_Wk[128 * 128];         // TRANSPOSED folded kproj: [c][o]

__device__ __forceinline__ ull pack2(float v) {
    ull r; asm("mov.b64 %0, {%1, %1};" : "=l"(r) : "f"(v)); return r;
}
__device__ __forceinline__ void ffma2(ull& d, ull a, ull b) {
    asm("fma.rn.f32x2 %0, %1, %2, %0;" : "+l"(d) : "l"(a), "l"(b));
}
__device__ __forceinline__ float2 unpack2(ull v) {
    float2 f; asm("mov.b64 {%0, %1}, %2;" : "=f"(f.x), "=f"(f.y) : "l"(v)); return f;
}

// ---------------------------------------------------------------------------
__global__ void fold_kernel(const float* __restrict__ qw, const float* __restrict__ nq,
                            const float* __restrict__ kw, const float* __restrict__ nk) {
    int i = blockIdx.x * 256 + threadIdx.x;   // i = c*128 + o
    if (i < 128 * 128) {
        int c = i >> 7, o = i & 127;
        g_Wq[i] = qw[o * 128 + c] * nq[c];
        g_Wk[i] = kw[o * 128 + c] * nk[c];
    }
}

__global__ void vtrans_kernel(const float* __restrict__ v) {
    int i = blockIdx.x * 256 + threadIdx.x;
    if (i < 32 * 32 * 128) {
        int c = i >> 10, p = i & 1023;
        g_vt[p * 128 + c] = v[i];
    }
}

// ---------------------------------------------------------------------------
// Direct 3x3 conv, 128->128ch over 128x128, f32x2, DOUBLE-BUFFERED smem.
// CTA: 16 oc x 16x16 pixels, 256 threads, 8 packed oc-pair accumulators.
__global__ __launch_bounds__(256) void conv3_kernel(const float* __restrict__ x,
                                                    const float* __restrict__ w) {
    __shared__ __align__(16) float sIn[2][8][18][18];
    __shared__ __align__(16) float sW[2][8][9][16];
    int ocb = blockIdx.x, by = blockIdx.y, bx = blockIdx.z;
    int tid = threadIdx.x;
    int ty = tid >> 4, tx = tid & 15;
    int gy0 = by * 16 - 1, gx0 = bx * 16 - 1;

    ull acc2[8];
#pragma unroll
    for (int i = 0; i < 8; i++) acc2[i] = 0ULL;

    float pin[11], pw[5];

    // prefetch ic-block into registers
    auto fetch = [&](int ic0) {
#pragma unroll
        for (int j = 0; j < 11; j++) {
            int idx = tid + 256 * j;
            float v = 0.f;
            if (idx < 2592) {
                int icl = idx / 324;
                int r = idx - icl * 324;
                int py = r / 18, px = r - py * 18;
                int gy = gy0 + py, gx = gx0 + px;
                if (gy >= 0 && gy < 128 && gx >= 0 && gx < 128)
                    v = __ldg(x + (ic0 + icl) * 16384 + gy * 128 + gx);
            }
            pin[j] = v;
        }
#pragma unroll
        for (int j = 0; j < 5; j++) {
            int idx = tid + 256 * j;
            float v = 0.f;
            if (idx < 1152) {
                int o = idx & 15;
                int k = (idx >> 4) % 9;
                int icl = idx / 144;
                v = __ldg(w + ((ocb * 16 + o) * 128 + ic0 + icl) * 9 + k);
            }
            pw[j] = v;
        }
    };
    auto stage = [&](int b) {
#pragma unroll
        for (int j = 0; j < 11; j++) {
            int idx = tid + 256 * j;
            if (idx < 2592) {
                int icl = idx / 324;
                int r = idx - icl * 324;
                int py = r / 18, px = r - py * 18;
                sIn[b][icl][py][px] = pin[j];
            }
        }
#pragma unroll
        for (int j = 0; j < 5; j++) {
            int idx = tid + 256 * j;
            if (idx < 1152) {
                int o = idx & 15;
                int k = (idx >> 4) % 9;
                int icl = idx / 144;
                sW[b][icl][k][o] = pw[j];
            }
        }
    };

    fetch(0);
    stage(0);
    __syncthreads();

    for (int ib = 0; ib < 16; ib++) {
        int b = ib & 1;
        if (ib < 15) fetch((ib + 1) * 8);
#pragma unroll
        for (int icl = 0; icl < 8; icl++) {
            ull iv2[9];
#pragma unroll
            for (int dy = 0; dy < 3; dy++)
#pragma unroll
                for (int dx = 0; dx < 3; dx++)
                    iv2[dy * 3 + dx] = pack2(sIn[b][icl][ty + dy][tx + dx]);
#pragma unroll
            for (int k = 0; k < 9; k++) {
                const ulonglong2* wp = (const ulonglong2*)&sW[b][icl][k][0];
                ulonglong2 wa = wp[0], wb = wp[1], wc = wp[2], wd = wp[3];
                ull iv = iv2[k];
                ffma2(acc2[0], wa.x, iv); ffma2(acc2[1], wa.y, iv);
                ffma2(acc2[2], wb.x, iv); ffma2(acc2[3], wb.y, iv);
                ffma2(acc2[4], wc.x, iv); ffma2(acc2[5], wc.y, iv);
                ffma2(acc2[6], wd.x, iv); ffma2(acc2[7], wd.y, iv);
            }
        }
        if (ib < 15) stage(1 - b);
        __syncthreads();
    }
    int y = by * 16 + ty, xx = bx * 16 + tx;
#pragma unroll
    for (int i = 0; i < 8; i++) {
        float2 f = unpack2(acc2[i]);
        g_qc[(ocb * 16 + 2 * i) * 16384 + y * 128 + xx] = f.x;
        g_qc[(ocb * 16 + 2 * i + 1) * 16384 + y * 128 + xx] = f.y;
    }
}

// ---------------------------------------------------------------------------
// Fused RMSNorm + 1x1 projection GEMM, weights fully staged in smem.
// CTA: 64 pixels x 128 oc, 256 threads, thread = 4 px x 8 oc.
__global__ __launch_bounds__(256) void proj_kernel(const float* __restrict__ xin,
                                                   const float* __restrict__ Wt,
                                                   const float* __restrict__ bias,
                                                   float* __restrict__ outp, int HW) {
    extern __shared__ __align__(16) float psm[];
    float* sW = psm;                // [128][128] = 64KB
    float* xs = sW + 128 * 128;     // [128][64]  = 32KB
    float* red = xs + 128 * 64;     // [4][64]
    float* rs = red + 4 * 64;       // [64]
    int tid = threadIdx.x;
    int p0 = blockIdx.x * 64;

    float4* sW4 = (float4*)sW;
    const float4* Wt4 = (const float4*)Wt;
#pragma unroll
    for (int j = 0; j < 16; j++) sW4[tid + 256 * j] = Wt4[tid + 256 * j];

    float4* xs4 = (float4*)xs;
    const float4* xin4 = (const float4*)xin;
#pragma unroll
    for (int j = 0; j < 8; j++) {
        int idx = tid + 256 * j;
        int c = idx >> 4, seg = idx & 15;
        xs4[idx] = xin4[c * (HW >> 2) + (p0 >> 2) + seg];
    }
    __syncthreads();
    {
        int px = tid & 63, g = tid >> 6;
        float s = 0.f;
#pragma unroll
        for (int j = 0; j < 32; j++) {
            float v = xs[(g * 32 + j) * 64 + px];
            s += v * v;
        }
        red[g * 64 + px] = s;
    }
    __syncthreads();
    if (tid < 64)
        rs[tid] = rsqrtf((red[tid] + red[64 + tid] + red[128 + tid] + red[192 + tid]) *
                         (1.f / 128.f) + EPSF);
    __syncthreads();

    int px4 = tid & 15;            // pixel group (4 px)
    int ocg = tid >> 4;            // oc group (8 oc)
    ull acc[4][4];
#pragma unroll
    for (int i = 0; i < 4; i++)
#pragma unroll
        for (int j = 0; j < 4; j++) acc[i][j] = 0ULL;

#pragma unroll 4
    for (int c = 0; c < 128; c++) {
        float4 xa = xs4[c * 16 + px4];
        ull x0 = pack2(xa.x), x1 = pack2(xa.y), x2 = pack2(xa.z), x3 = pack2(xa.w);
        const ulonglong2* wp = (const ulonglong2*)(sW + c * 128 + ocg * 8);
        ulonglong2 w0 = wp[0], w1 = wp[1];
        ffma2(acc[0][0], w0.x, x0); ffma2(acc[0][1], w0.y, x0);
        ffma2(acc[0][2], w1.x, x0); ffma2(acc[0][3], w1.y, x0);
        ffma2(acc[1][0], w0.x, x1); ffma2(acc[1][1], w0.y, x1);
        ffma2(acc[1][2], w1.x, x1); ffma2(acc[1][3], w1.y, x1);
        ffma2(acc[2][0], w0.x, x2); ffma2(acc[2][1], w0.y, x2);
        ffma2(acc[2][2], w1.x, x2); ffma2(acc[2][3], w1.y, x2);
        ffma2(acc[3][0], w0.x, x3); ffma2(acc[3][1], w0.y, x3);
        ffma2(acc[3][2], w1.x, x3); ffma2(acc[3][3], w1.y, x3);
    }
    float4 bA = __ldg((const float4*)(bias + ocg * 8));
    float4 bB = __ldg((const float4*)(bias + ocg * 8 + 4));
#pragma unroll
    for (int p = 0; p < 4; p++) {
        float r = rs[px4 * 4 + p];
        float2 f0 = unpack2(acc[p][0]), f1 = unpack2(acc[p][1]);
        float2 f2 = unpack2(acc[p][2]), f3 = unpack2(acc[p][3]);
        float4 oA = make_float4(f0.x * r + bA.x, f0.y * r + bA.y,
                                f1.x * r + bA.z, f1.y * r + bA.w);
        float4 oB = make_float4(f2.x * r + bB.x, f2.y * r + bB.y,
                                f3.x * r + bB.z, f3.y * r + bB.w);
        float4* op = (float4*)(outp + (p0 + px4 * 4 + p) * 128 + ocg * 8);
        op[0] = oA; op[1] = oB;
    }
}

// ---------------------------------------------------------------------------
// Attention: NO k/v/q smem staging (L1/L2-resident reads). smem = probs only.
// 1 CTA per 4x4 query block (grid 1024), 128 threads, ~16KB smem.
__global__ __launch_bounds__(128) void attn_kernel(float* __restrict__ outp) {
    __shared__ float pr[64][50];     // [q*4+h][49]
    __shared__ float amT[49][16];    // head-mean, transposed [kk][q]
    int tid = threadIdx.x;
    int iq = blockIdx.x >> 5, jq = blockIdx.x & 31;
    int sy = iq - 3; sy = sy < 0 ? 0 : (sy > 25 ? 25 : sy);
    int sx = jq - 3; sx = sx < 0 ? 0 : (sx > 25 ? 25 : sx);
    int base = sy * 32 + sx;

    // Phase 1: logits + softmax. warp = head; thread = (q, key-half s).
    {
        int h = tid >> 5, qi = (tid >> 1) & 15, s = tid & 1;
        int y = iq * 4 + (qi >> 2), xx = jq * 4 + (qi & 3);
        const ulonglong2* qp = (const ulonglong2*)(g_qf + (y * 128 + xx) * 128 + h * 32);
        ull qr[16];
#pragma unroll
        for (int j = 0; j < 8; j++) { ulonglong2 v = __ldg(qp + j); qr[2 * j] = v.x; qr[2 * j + 1] = v.y; }
        int k0 = s * 24;
        float l[25];
        float mx = -1e30f;
#pragma unroll
        for (int j = 0; j < 25; j++) {
            int kk = k0 + j;
            int m = kk / 7, n = kk - m * 7;
            const ulonglong2* kp = (const ulonglong2*)(g_kf + (base + m * 32 + n) * 128 + h * 32);
            ull a = 0ULL;
#pragma unroll
            for (int t = 0; t < 8; t++) {
                ulonglong2 kv = __ldg(kp + t);
                ffma2(a, qr[2 * t], kv.x);
                ffma2(a, qr[2 * t + 1], kv.y);
            }
            float2 f = unpack2(a);
            float sc = (f.x + f.y) * 0.17677669529663687f;   // 32^-0.5
            l[j] = sc;
            mx = fmaxf(mx, sc);
        }
        mx = fmaxf(mx, __shfl_xor_sync(0xffffffffu, mx, 1));
        float sum = 0.f;
#pragma unroll
        for (int j = 0; j < 25; j++) {
            if (s && j == 0) continue;   // key 24 duplicated on s=1
            float e = __expf(l[j] - mx);
            l[j] = e;
            sum += e;
        }
        sum += __shfl_xor_sync(0xffffffffu, sum, 1);
        float inv = 1.f / sum;
        float* prow = pr[qi * 4 + h];
#pragma unroll
        for (int j = 0; j < 25; j++) {
            if (s && j == 0) continue;
            prow[k0 + j] = l[j] * inv;
        }
    }
    __syncthreads();

    for (int i = tid; i < 16 * 49; i += 128) {
        int q = i / 49, kk = i - q * 49;
        amT[kk][q] = 0.25f * (pr[q * 4 + 0][kk] + pr[q * 4 + 1][kk] +
                              pr[q * 4 + 2][kk] + pr[q * 4 + 3][kk]);
    }
    __syncthreads();

    // Phase 2: V contraction, f32x2 over query-x pairs. warp = qy.
    {
        int qy = tid >> 5, cb = tid & 31;
        ull acc[4][2];
#pragma unroll
        for (int j = 0; j < 4; j++) { acc[j][0] = 0ULL; acc[j][1] = 0ULL; }
#pragma unroll
        for (int kk = 0; kk < 49; kk++) {
            int m = kk / 7, n = kk - m * 7;                // compile-time folds
            const float* vp = g_vt + (base + m * 32 + n) * 128 + cb;
            const ull* ap = (const ull*)(&amT[kk][qy * 4]);
            ull a01 = ap[0], a23 = ap[1];
#pragma unroll
            for (int j = 0; j < 4; j++) {
                ull vv = pack2(__ldg(vp + 32 * j));
                ffma2(acc[j][0], a01, vv);
                ffma2(acc[j][1], a23, vv);
            }
        }
        int y = iq * 4 + qy;
#pragma unroll
        for (int j = 0; j < 4; j++) {
            int c = cb + 32 * j;
            float2 r01 = unpack2(acc[j][0]);
            float2 r23 = unpack2(acc[j][1]);
            float4* op = (float4*)(outp + c * 16384 + y * 128 + jq * 4);
            op[0] = make_float4(r01.x, r01.y, r23.x, r23.y);
        }
    }
}

// ---------------------------------------------------------------------------
extern "C" void kernel_launch(void* const* d_in, const int* in_sizes, int n_in,
                              void* d_out, int out_size) {
    (void)in_sizes; (void)n_in; (void)out_size;
    const float* q  = (const float*)d_in[0];
    const float* k  = (const float*)d_in[1];
    const float* v  = (const float*)d_in[2];
    const float* cw = (const float*)d_in[3];
    const float* nq = (const float*)d_in[4];
    const float* nk = (const float*)d_in[5];
    const float* qw = (const float*)d_in[6];
    const float* qb = (const float*)d_in[7];
    const float* kw = (const float*)d_in[8];
    const float* kb = (const float*)d_in[9];
    float* out = (float*)d_out;

    void *qc_p, *qf_p, *kf_p, *wq_p, *wk_p;
    cudaGetSymbolAddress(&qc_p, g_qc);
    cudaGetSymbolAddress(&qf_p, g_qf);
    cudaGetSymbolAddress(&kf_p, g_kf);
    cudaGetSymbolAddress(&wq_p, g_Wq);
    cudaGetSymbolAddress(&wk_p, g_Wk);

    fold_kernel<<<64, 256>>>(qw, nq, kw, nk);
    vtrans_kernel<<<512, 256>>>(v);
    conv3_kernel<<<dim3(8, 8, 8), 256>>>(q, cw);

    const int proj_smem = (128 * 128 + 128 * 64 + 4 * 64 + 64) * 4;  // 98560 B
    cudaFuncSetAttribute(proj_kernel, cudaFuncAttributeMaxDynamicSharedMemorySize, proj_smem);
    proj_kernel<<<256, 256, proj_smem>>>((const float*)qc_p, (const float*)wq_p, qb,
                                         (float*)qf_p, 16384);
    proj_kernel<<<16, 256, proj_smem>>>(k, (const float*)wk_p, kb, (float*)kf_p, 1024);

    attn_kernel<<<1024, 128>>>(out);
}

// round 4
// speedup vs baseline: 1.2727x; 1.0808x over previous
#include <cuda_runtime.h>

// ---------------------------------------------------------------------------
// NATTEN cross-attention block, fp32 + packed FFMA2.
// conv3x3(q) -> rmsnorm+qproj -> rmsnorm+kproj(k) -> attention.
// Attention: upsample-by-4 + dilation-4 NATTEN == each 4x4 query block attends
// to a 7x7 window of the ORIGINAL 32x32 k/v grid, start clamp(iq-3, 0, 25).
// ---------------------------------------------------------------------------

#define EPSF 1.1920928955078125e-7f
typedef unsigned long long ull;

__device__ float g_qc[128 * 128 * 128];   // conv output, NCHW
__device__ float g_qf[128 * 128 * 128];   // q final, pixel-major [pix][c]
__device__ float g_kf[32 * 32 * 128];     // k final, pixel-major
__device__ float g_vt[32 * 32 * 128];     // v transposed, pixel-major
__device__ float g_Wq[128 * 128];         // TRANSPOSED folded qproj: [c][o]
__device__ float g_Wk[128 * 128];         // TRANSPOSED folded kproj: [c][o]

__device__ __forceinline__ ull pack2(float v) {
    ull r; asm("mov.b64 %0, {%1, %1};" : "=l"(r) : "f"(v)); return r;
}
__device__ __forceinline__ void ffma2(ull& d, ull a, ull b) {
    asm("fma.rn.f32x2 %0, %1, %2, %0;" : "+l"(d) : "l"(a), "l"(b));
}
__device__ __forceinline__ float2 unpack2(ull v) {
    float2 f; asm("mov.b64 {%0, %1}, %2;" : "=f"(f.x), "=f"(f.y) : "l"(v)); return f;
}

// ---------------------------------------------------------------------------
__global__ void fold_kernel(const float* __restrict__ qw, const float* __restrict__ nq,
                            const float* __restrict__ kw, const float* __restrict__ nk) {
    int i = blockIdx.x * 256 + threadIdx.x;   // i = c*128 + o
    if (i < 128 * 128) {
        int c = i >> 7, o = i & 127;
        g_Wq[i] = qw[o * 128 + c] * nq[c];
        g_Wk[i] = kw[o * 128 + c] * nk[c];
    }
}

__global__ void vtrans_kernel(const float* __restrict__ v) {
    int i = blockIdx.x * 256 + threadIdx.x;
    if (i < 32 * 32 * 128) {
        int c = i >> 10, p = i & 1023;
        g_vt[p * 128 + c] = v[i];
    }
}

// ---------------------------------------------------------------------------
// Direct 3x3 conv, 128->128ch over 128x128, f32x2, double-buffered smem.
__global__ __launch_bounds__(256) void conv3_kernel(const float* __restrict__ x,
                                                    const float* __restrict__ w) {
    __shared__ __align__(16) float sIn[2][8][18][18];
    __shared__ __align__(16) float sW[2][8][9][16];
    int ocb = blockIdx.x, by = blockIdx.y, bx = blockIdx.z;
    int tid = threadIdx.x;
    int ty = tid >> 4, tx = tid & 15;
    int gy0 = by * 16 - 1, gx0 = bx * 16 - 1;

    ull acc2[8];
#pragma unroll
    for (int i = 0; i < 8; i++) acc2[i] = 0ULL;

    float pin[11], pw[5];

    auto fetch = [&](int ic0) {
#pragma unroll
        for (int j = 0; j < 11; j++) {
            int idx = tid + 256 * j;
            float v = 0.f;
            if (idx < 2592) {
                int icl = idx / 324;
                int r = idx - icl * 324;
                int py = r / 18, px = r - py * 18;
                int gy = gy0 + py, gx = gx0 + px;
                if (gy >= 0 && gy < 128 && gx >= 0 && gx < 128)
                    v = __ldg(x + (ic0 + icl) * 16384 + gy * 128 + gx);
            }
            pin[j] = v;
        }
#pragma unroll
        for (int j = 0; j < 5; j++) {
            int idx = tid + 256 * j;
            float v = 0.f;
            if (idx < 1152) {
                int o = idx & 15;
                int k = (idx >> 4) % 9;
                int icl = idx / 144;
                v = __ldg(w + ((ocb * 16 + o) * 128 + ic0 + icl) * 9 + k);
            }
            pw[j] = v;
        }
    };
    auto stage = [&](int b) {
#pragma unroll
        for (int j = 0; j < 11; j++) {
            int idx = tid + 256 * j;
            if (idx < 2592) {
                int icl = idx / 324;
                int r = idx - icl * 324;
                int py = r / 18, px = r - py * 18;
                sIn[b][icl][py][px] = pin[j];
            }
        }
#pragma unroll
        for (int j = 0; j < 5; j++) {
            int idx = tid + 256 * j;
            if (idx < 1152) {
                int o = idx & 15;
                int k = (idx >> 4) % 9;
                int icl = idx / 144;
                sW[b][icl][k][o] = pw[j];
            }
        }
    };

    fetch(0);
    stage(0);
    __syncthreads();

    for (int ib = 0; ib < 16; ib++) {
        int b = ib & 1;
        if (ib < 15) fetch((ib + 1) * 8);
#pragma unroll
        for (int icl = 0; icl < 8; icl++) {
            ull iv2[9];
#pragma unroll
            for (int dy = 0; dy < 3; dy++)
#pragma unroll
                for (int dx = 0; dx < 3; dx++)
                    iv2[dy * 3 + dx] = pack2(sIn[b][icl][ty + dy][tx + dx]);
#pragma unroll
            for (int k = 0; k < 9; k++) {
                const ulonglong2* wp = (const ulonglong2*)&sW[b][icl][k][0];
                ulonglong2 wa = wp[0], wb = wp[1], wc = wp[2], wd = wp[3];
                ull iv = iv2[k];
                ffma2(acc2[0], wa.x, iv); ffma2(acc2[1], wa.y, iv);
                ffma2(acc2[2], wb.x, iv); ffma2(acc2[3], wb.y, iv);
                ffma2(acc2[4], wc.x, iv); ffma2(acc2[5], wc.y, iv);
                ffma2(acc2[6], wd.x, iv); ffma2(acc2[7], wd.y, iv);
            }
        }
        if (ib < 15) stage(1 - b);
        __syncthreads();
    }
    int y = by * 16 + ty, xx = bx * 16 + tx;
#pragma unroll
    for (int i = 0; i < 8; i++) {
        float2 f = unpack2(acc2[i]);
        g_qc[(ocb * 16 + 2 * i) * 16384 + y * 128 + xx] = f.x;
        g_qc[(ocb * 16 + 2 * i + 1) * 16384 + y * 128 + xx] = f.y;
    }
}

// ---------------------------------------------------------------------------
// Fused RMSNorm + 1x1 projection GEMM, weights staged in smem.
__global__ __launch_bounds__(256) void proj_kernel(const float* __restrict__ xin,
                                                   const float* __restrict__ Wt,
                                                   const float* __restrict__ bias,
                                                   float* __restrict__ outp, int HW) {
    extern __shared__ __align__(16) float psm[];
    float* sW = psm;                // [128][128] = 64KB
    float* xs = sW + 128 * 128;     // [128][64]  = 32KB
    float* red = xs + 128 * 64;     // [4][64]
    float* rs = red + 4 * 64;       // [64]
    int tid = threadIdx.x;
    int p0 = blockIdx.x * 64;

    float4* sW4 = (float4*)sW;
    const float4* Wt4 = (const float4*)Wt;
#pragma unroll
    for (int j = 0; j < 16; j++) sW4[tid + 256 * j] = Wt4[tid + 256 * j];

    float4* xs4 = (float4*)xs;
    const float4* xin4 = (const float4*)xin;
#pragma unroll
    for (int j = 0; j < 8; j++) {
        int idx = tid + 256 * j;
        int c = idx >> 4, seg = idx & 15;
        xs4[idx] = xin4[c * (HW >> 2) + (p0 >> 2) + seg];
    }
    __syncthreads();
    {
        int px = tid & 63, g = tid >> 6;
        float s = 0.f;
#pragma unroll
        for (int j = 0; j < 32; j++) {
            float v = xs[(g * 32 + j) * 64 + px];
            s += v * v;
        }
        red[g * 64 + px] = s;
    }
    __syncthreads();
    if (tid < 64)
        rs[tid] = rsqrtf((red[tid] + red[64 + tid] + red[128 + tid] + red[192 + tid]) *
                         (1.f / 128.f) + EPSF);
    __syncthreads();

    int px4 = tid & 15;
    int ocg = tid >> 4;
    ull acc[4][4];
#pragma unroll
    for (int i = 0; i < 4; i++)
#pragma unroll
        for (int j = 0; j < 4; j++) acc[i][j] = 0ULL;

#pragma unroll 4
    for (int c = 0; c < 128; c++) {
        float4 xa = xs4[c * 16 + px4];
        ull x0 = pack2(xa.x), x1 = pack2(xa.y), x2 = pack2(xa.z), x3 = pack2(xa.w);
        const ulonglong2* wp = (const ulonglong2*)(sW + c * 128 + ocg * 8);
        ulonglong2 w0 = wp[0], w1 = wp[1];
        ffma2(acc[0][0], w0.x, x0); ffma2(acc[0][1], w0.y, x0);
        ffma2(acc[0][2], w1.x, x0); ffma2(acc[0][3], w1.y, x0);
        ffma2(acc[1][0], w0.x, x1); ffma2(acc[1][1], w0.y, x1);
        ffma2(acc[1][2], w1.x, x1); ffma2(acc[1][3], w1.y, x1);
        ffma2(acc[2][0], w0.x, x2); ffma2(acc[2][1], w0.y, x2);
        ffma2(acc[2][2], w1.x, x2); ffma2(acc[2][3], w1.y, x2);
        ffma2(acc[3][0], w0.x, x3); ffma2(acc[3][1], w0.y, x3);
        ffma2(acc[3][2], w1.x, x3); ffma2(acc[3][3], w1.y, x3);
    }
    float4 bA = __ldg((const float4*)(bias + ocg * 8));
    float4 bB = __ldg((const float4*)(bias + ocg * 8 + 4));
#pragma unroll
    for (int p = 0; p < 4; p++) {
        float r = rs[px4 * 4 + p];
        float2 f0 = unpack2(acc[p][0]), f1 = unpack2(acc[p][1]);
        float2 f2 = unpack2(acc[p][2]), f3 = unpack2(acc[p][3]);
        float4 oA = make_float4(f0.x * r + bA.x, f0.y * r + bA.y,
                                f1.x * r + bA.z, f1.y * r + bA.w);
        float4 oB = make_float4(f2.x * r + bB.x, f2.y * r + bB.y,
                                f3.x * r + bB.z, f3.y * r + bB.w);
        float4* op = (float4*)(outp + (p0 + px4 * 4 + p) * 128 + ocg * 8);
        op[0] = oA; op[1] = oB;
    }
}

// ---------------------------------------------------------------------------
// Attention. 1 CTA per 4x4 query block (grid 1024), 128 threads.
// k-window + q-tile staged in smem with per-row column rotation
// phys_col = (col + (row>>1)) & 31  -> conflict-free phase-1 reads.
// smem: ks[49*132] qs[16*132] lg[4*16*52] amT[49*16]  = 50768 B.
__global__ __launch_bounds__(128, 4) void attn_kernel(float* __restrict__ outp) {
    extern __shared__ __align__(16) float asm_[];
    float* ks = asm_;                // 49 rows x 132 (33 float4/row, rotated)
    float* qs = ks + 49 * 132;       // 16 rows x 132
    float* lg = qs + 16 * 132;       // [h][q][52] logits -> probs in place
    float* amT = lg + 4 * 16 * 52;   // [49][16] head-mean transposed
    int tid = threadIdx.x;
    int iq = blockIdx.x >> 5, jq = blockIdx.x & 31;
    int sy = iq - 3; sy = sy < 0 ? 0 : (sy > 25 ? 25 : sy);
    int sx = jq - 3; sx = sx < 0 ? 0 : (sx > 25 ? 25 : sx);
    int base = sy * 32 + sx;

    // Stage k window + q tile (rotated columns)
    {
        float4* ks4 = (float4*)ks;
        float4* qs4 = (float4*)qs;
        const float4* kf4 = (const float4*)g_kf;
        const float4* qf4 = (const float4*)g_qf;
        for (int i = tid; i < 49 * 32; i += 128) {
            int kk = i >> 5, c4 = i & 31;
            int m = kk / 7, n = kk - m * 7;
            ks4[kk * 33 + ((c4 + (kk >> 1)) & 31)] = kf4[(base + m * 32 + n) * 32 + c4];
        }
        for (int i = tid; i < 16 * 32; i += 128) {
            int r = i >> 5, c4 = i & 31;
            int y = iq * 4 + (r >> 2), xx = jq * 4 + (r & 3);
            qs4[r * 33 + ((c4 + (r >> 1)) & 31)] = qf4[(y * 128 + xx) * 32 + c4];
        }
    }
    __syncthreads();

    // Phase 1: logits. thread = (head, q-pair, key-quarter).
    {
        int h = tid >> 5, lane = tid & 31;
        int qh = lane >> 2, kq = lane & 3;
        ull qr[2][16];
#pragma unroll
        for (int t = 0; t < 2; t++) {
            int qi = qh * 2 + t;
            const ulonglong2* qrow = (const ulonglong2*)((const float4*)qs + qi * 33);
            int rot = qi >> 1;
#pragma unroll
            for (int seg = 0; seg < 8; seg++) {
                ulonglong2 v = qrow[(h * 8 + seg + rot) & 31];
                qr[t][2 * seg] = v.x; qr[t][2 * seg + 1] = v.y;
            }
        }
        for (int j = 0; j < 13; j++) {
            if (j == 12 && kq != 3) break;
            int kk = kq * 12 + j;
            const ulonglong2* krow = (const ulonglong2*)((const float4*)ks + kk * 33);
            int rot = kk >> 1;
            ull kr[16];
#pragma unroll
            for (int seg = 0; seg < 8; seg++) {
                ulonglong2 v = krow[(h * 8 + seg + rot) & 31];
                kr[2 * seg] = v.x; kr[2 * seg + 1] = v.y;
            }
#pragma unroll
            for (int t = 0; t < 2; t++) {
                ull a = 0ULL;
#pragma unroll
                for (int u = 0; u < 16; u++) ffma2(a, qr[t][u], kr[u]);
                float2 f = unpack2(a);
                lg[h * 832 + (qh * 2 + t) * 52 + kk] = (f.x + f.y) * 0.17677669529663687f;
            }
        }
    }
    __syncthreads();

    // Softmax per (q, h) over 49 keys (64 threads), in place.
    if (tid < 64) {
        int q = tid & 15, h = tid >> 4;
        float* row = lg + h * 832 + q * 52;
        float mx = -1e30f;
#pragma unroll
        for (int kk = 0; kk < 49; kk++) mx = fmaxf(mx, row[kk]);
        float sum = 0.f;
#pragma unroll
        for (int kk = 0; kk < 49; kk++) { float e = __expf(row[kk] - mx); row[kk] = e; sum += e; }
        float inv = 1.f / sum;
#pragma unroll
        for (int kk = 0; kk < 49; kk++) row[kk] *= inv;
    }
    __syncthreads();

    // Head mean, transposed: amT[kk][q]
    for (int i = tid; i < 784; i += 128) {
        int q = i / 49, kk = i - q * 49;
        amT[kk * 16 + q] = 0.25f * (lg[q * 52 + kk] + lg[832 + q * 52 + kk] +
                                    lg[1664 + q * 52 + kk] + lg[2496 + q * 52 + kk]);
    }
    __syncthreads();

    // Phase 2: V contraction. warp = qy (output row); coalesced L2 reads.
    {
        int qy = tid >> 5, cb = tid & 31;
        ull acc[4][2];
#pragma unroll
        for (int j = 0; j < 4; j++) { acc[j][0] = 0ULL; acc[j][1] = 0ULL; }
#pragma unroll
        for (int kk = 0; kk < 49; kk++) {
            int m = kk / 7, n = kk - m * 7;
            const float* vp = g_vt + (base + m * 32 + n) * 128 + cb;
            const ull* ap = (const ull*)(amT + kk * 16 + qy * 4);
            ull a01 = ap[0], a23 = ap[1];
#pragma unroll
            for (int j = 0; j < 4; j++) {
                ull vv = pack2(__ldg(vp + 32 * j));
                ffma2(acc[j][0], a01, vv);
                ffma2(acc[j][1], a23, vv);
            }
        }
        int y = iq * 4 + qy;
#pragma unroll
        for (int j = 0; j < 4; j++) {
            int c = cb + 32 * j;
            float2 r01 = unpack2(acc[j][0]);
            float2 r23 = unpack2(acc[j][1]);
            float4* op = (float4*)(outp + c * 16384 + y * 128 + jq * 4);
            op[0] = make_float4(r01.x, r01.y, r23.x, r23.y);
        }
    }
}

// ---------------------------------------------------------------------------
extern "C" void kernel_launch(void* const* d_in, const int* in_sizes, int n_in,
                              void* d_out, int out_size) {
    (void)in_sizes; (void)n_in; (void)out_size;
    const float* q  = (const float*)d_in[0];
    const float* k  = (const float*)d_in[1];
    const float* v  = (const float*)d_in[2];
    const float* cw = (const float*)d_in[3];
    const float* nq = (const float*)d_in[4];
    const float* nk = (const float*)d_in[5];
    const float* qw = (const float*)d_in[6];
    const float* qb = (const float*)d_in[7];
    const float* kw = (const float*)d_in[8];
    const float* kb = (const float*)d_in[9];
    float* out = (float*)d_out;

    void *qc_p, *qf_p, *kf_p, *wq_p, *wk_p;
    cudaGetSymbolAddress(&qc_p, g_qc);
    cudaGetSymbolAddress(&qf_p, g_qf);
    cudaGetSymbolAddress(&kf_p, g_kf);
    cudaGetSymbolAddress(&wq_p, g_Wq);
    cudaGetSymbolAddress(&wk_p, g_Wk);

    const int proj_smem = (128 * 128 + 128 * 64 + 4 * 64 + 64) * 4;  // 98560 B
    cudaFuncSetAttribute(proj_kernel, cudaFuncAttributeMaxDynamicSharedMemorySize, proj_smem);

    fold_kernel<<<64, 256>>>(qw, nq, kw, nk);
    vtrans_kernel<<<512, 256>>>(v);
    // k-proj is independent of conv — run it first so it overlaps nothing critical
    proj_kernel<<<16, 256, proj_smem>>>(k, (const float*)wk_p, kb, (float*)kf_p, 1024);
    conv3_kernel<<<dim3(8, 8, 8), 256>>>(q, cw);
    proj_kernel<<<256, 256, proj_smem>>>((const float*)qc_p, (const float*)wq_p, qb,
                                         (float*)qf_p, 16384);

    const int attn_smem = (49 * 132 + 16 * 132 + 4 * 16 * 52 + 49 * 16) * 4;  // 50768 B
    cudaFuncSetAttribute(attn_kernel, cudaFuncAttributeMaxDynamicSharedMemorySize, attn_smem);
    attn_kernel<<<1024, 128, attn_smem>>>(out);
}

// round 5
// speedup vs baseline: 1.7059x; 1.3404x over previous
#include <cuda_runtime.h>

// ---------------------------------------------------------------------------
// NATTEN cross-attention block, fp32 + packed FFMA2.
// conv3x3(q) -> rmsnorm+qproj -> rmsnorm+kproj(k) -> attention.
// Attention: upsample-by-4 + dilation-4 NATTEN == each 4x4 query block attends
// to a 7x7 window of the ORIGINAL 32x32 k/v grid, start clamp(iq-3, 0, 25).
// ---------------------------------------------------------------------------

#define EPSF 1.1920928955078125e-7f
typedef unsigned long long ull;

__device__ float g_qc[128 * 128 * 128];   // conv output, NCHW
__device__ float g_qf[128 * 128 * 128];   // q final, pixel-major [pix][c]
__device__ float g_kf[32 * 32 * 128];     // k final, pixel-major
__device__ float g_vt[32 * 32 * 128];     // v transposed, pixel-major
__device__ float g_Wq[128 * 128];         // TRANSPOSED folded qproj: [c][o]
__device__ float g_Wk[128 * 128];         // TRANSPOSED folded kproj: [c][o]

__device__ __forceinline__ ull pack2(float v) {
    ull r; asm("mov.b64 %0, {%1, %1};" : "=l"(r) : "f"(v)); return r;
}
__device__ __forceinline__ void ffma2(ull& d, ull a, ull b) {
    asm("fma.rn.f32x2 %0, %1, %2, %0;" : "+l"(d) : "l"(a), "l"(b));
}
__device__ __forceinline__ float2 unpack2(ull v) {
    float2 f; asm("mov.b64 {%0, %1}, %2;" : "=f"(f.x), "=f"(f.y) : "l"(v)); return f;
}

// ---------------------------------------------------------------------------
__global__ void fold_kernel(const float* __restrict__ qw, const float* __restrict__ nq,
                            const float* __restrict__ kw, const float* __restrict__ nk) {
    int i = blockIdx.x * 256 + threadIdx.x;   // i = c*128 + o
    if (i < 128 * 128) {
        int c = i >> 7, o = i & 127;
        g_Wq[i] = qw[o * 128 + c] * nq[c];
        g_Wk[i] = kw[o * 128 + c] * nk[c];
    }
}

__global__ void vtrans_kernel(const float* __restrict__ v) {
    int i = blockIdx.x * 256 + threadIdx.x;
    if (i < 32 * 32 * 128) {
        int c = i >> 10, p = i & 1023;
        g_vt[p * 128 + c] = v[i];
    }
}

// ---------------------------------------------------------------------------
// Direct 3x3 conv, 128->128ch over 128x128, f32x2, register-tiled.
// CTA: 32 oc x 16x16 pixels, 256 threads. Thread = 4 px x 8 oc (16 ull acc).
// Per ic: 6 input LDS.128 (packed once per row) + 18 weight LDS.128
// (broadcast) + 144 FFMA2  -> fma-pipe-bound.
__global__ __launch_bounds__(256, 2) void conv3_kernel(const float* __restrict__ x,
                                                       const float* __restrict__ w) {
    __shared__ __align__(16) float sIn[2][8][18][20];
    __shared__ __align__(16) float sW[2][8][9][32];
    int ocb = blockIdx.x, by = blockIdx.y, bx = blockIdx.z;
    int tid = threadIdx.x;
    int ty = tid >> 4;                 // 0..15
    int txg = (tid >> 2) & 3;          // 0..3 (4 px each)
    int ocg = tid & 3;                 // 0..3 (8 oc each)
    int gy0 = by * 16 - 1, gx0 = bx * 16 - 1;

    ull acc[4][4];                     // [px][ocpair]
#pragma unroll
    for (int p = 0; p < 4; p++)
#pragma unroll
        for (int j = 0; j < 4; j++) acc[p][j] = 0ULL;

    float pin[11], pw[9];

    auto fetch = [&](int ic0) {
#pragma unroll
        for (int j = 0; j < 11; j++) {
            int idx = tid + 256 * j;
            float v = 0.f;
            if (idx < 2592) {
                int icl = idx / 324;
                int r = idx - icl * 324;
                int py = r / 18, px = r - py * 18;
                int gy = gy0 + py, gx = gx0 + px;
                if (gy >= 0 && gy < 128 && gx >= 0 && gx < 128)
                    v = __ldg(x + (ic0 + icl) * 16384 + gy * 128 + gx);
            }
            pin[j] = v;
        }
#pragma unroll
        for (int j = 0; j < 9; j++) {
            int idx = tid + 256 * j;   // < 2304 always
            int icl = idx / 288;
            int r = idx - icl * 288;
            int k = r >> 5, o = r & 31;
            pw[j] = __ldg(w + ((ocb * 32 + o) * 128 + ic0 + icl) * 9 + k);
        }
    };
    auto stage = [&](int b) {
#pragma unroll
        for (int j = 0; j < 11; j++) {
            int idx = tid + 256 * j;
            if (idx < 2592) {
                int icl = idx / 324;
                int r = idx - icl * 324;
                int py = r / 18, px = r - py * 18;
                sIn[b][icl][py][px] = pin[j];
            }
        }
#pragma unroll
        for (int j = 0; j < 9; j++) {
            int idx = tid + 256 * j;
            int icl = idx / 288;
            int r = idx - icl * 288;
            int k = r >> 5, o = r & 31;
            sW[b][icl][k][o] = pw[j];
        }
    };

    fetch(0);
    stage(0);
    __syncthreads();

    for (int ib = 0; ib < 16; ib++) {
        int b = ib & 1;
        if (ib < 15) fetch((ib + 1) * 8);
#pragma unroll
        for (int icl = 0; icl < 8; icl++) {
#pragma unroll
            for (int dy = 0; dy < 3; dy++) {
                const float4* rp = (const float4*)&sIn[b][icl][ty + dy][txg * 4];
                float4 ra = rp[0], rb = rp[1];
                ull p2[6];
                p2[0] = pack2(ra.x); p2[1] = pack2(ra.y); p2[2] = pack2(ra.z);
                p2[3] = pack2(ra.w); p2[4] = pack2(rb.x); p2[5] = pack2(rb.y);
#pragma unroll
                for (int dx = 0; dx < 3; dx++) {
                    const ulonglong2* wp =
                        (const ulonglong2*)&sW[b][icl][dy * 3 + dx][ocg * 8];
                    ulonglong2 wA = wp[0], wB = wp[1];
#pragma unroll
                    for (int p = 0; p < 4; p++) {
                        ull iv = p2[dx + p];
                        ffma2(acc[p][0], wA.x, iv);
                        ffma2(acc[p][1], wA.y, iv);
                        ffma2(acc[p][2], wB.x, iv);
                        ffma2(acc[p][3], wB.y, iv);
                    }
                }
            }
        }
        if (ib < 15) stage(1 - b);
        __syncthreads();
    }

    int y = by * 16 + ty;
    int xbase = bx * 16 + txg * 4;
#pragma unroll
    for (int j = 0; j < 4; j++) {
        float2 f0 = unpack2(acc[0][j]);
        float2 f1 = unpack2(acc[1][j]);
        float2 f2 = unpack2(acc[2][j]);
        float2 f3 = unpack2(acc[3][j]);
        int oc0 = ocb * 32 + ocg * 8 + 2 * j;
        float4* op0 = (float4*)(g_qc + oc0 * 16384 + y * 128 + xbase);
        float4* op1 = (float4*)(g_qc + (oc0 + 1) * 16384 + y * 128 + xbase);
        op0[0] = make_float4(f0.x, f1.x, f2.x, f3.x);
        op1[0] = make_float4(f0.y, f1.y, f2.y, f3.y);
    }
}

// ---------------------------------------------------------------------------
// Fused RMSNorm + 1x1 projection GEMM, weights staged in smem.
__global__ __launch_bounds__(256) void proj_kernel(const float* __restrict__ xin,
                                                   const float* __restrict__ Wt,
                                                   const float* __restrict__ bias,
                                                   float* __restrict__ outp, int HW) {
    extern __shared__ __align__(16) float psm[];
    float* sW = psm;                // [128][128] = 64KB
    float* xs = sW + 128 * 128;     // [128][64]  = 32KB
    float* red = xs + 128 * 64;     // [4][64]
    float* rs = red + 4 * 64;       // [64]
    int tid = threadIdx.x;
    int p0 = blockIdx.x * 64;

    float4* sW4 = (float4*)sW;
    const float4* Wt4 = (const float4*)Wt;
#pragma unroll
    for (int j = 0; j < 16; j++) sW4[tid + 256 * j] = Wt4[tid + 256 * j];

    float4* xs4 = (float4*)xs;
    const float4* xin4 = (const float4*)xin;
#pragma unroll
    for (int j = 0; j < 8; j++) {
        int idx = tid + 256 * j;
        int c = idx >> 4, seg = idx & 15;
        xs4[idx] = xin4[c * (HW >> 2) + (p0 >> 2) + seg];
    }
    __syncthreads();
    {
        int px = tid & 63, g = tid >> 6;
        float s = 0.f;
#pragma unroll
        for (int j = 0; j < 32; j++) {
            float v = xs[(g * 32 + j) * 64 + px];
            s += v * v;
        }
        red[g * 64 + px] = s;
    }
    __syncthreads();
    if (tid < 64)
        rs[tid] = rsqrtf((red[tid] + red[64 + tid] + red[128 + tid] + red[192 + tid]) *
                         (1.f / 128.f) + EPSF);
    __syncthreads();

    int px4 = tid & 15;
    int ocg = tid >> 4;
    ull acc[4][4];
#pragma unroll
    for (int i = 0; i < 4; i++)
#pragma unroll
        for (int j = 0; j < 4; j++) acc[i][j] = 0ULL;

#pragma unroll 4
    for (int c = 0; c < 128; c++) {
        float4 xa = xs4[c * 16 + px4];
        ull x0 = pack2(xa.x), x1 = pack2(xa.y), x2 = pack2(xa.z), x3 = pack2(xa.w);
        const ulonglong2* wp = (const ulonglong2*)(sW + c * 128 + ocg * 8);
        ulonglong2 w0 = wp[0], w1 = wp[1];
        ffma2(acc[0][0], w0.x, x0); ffma2(acc[0][1], w0.y, x0);
        ffma2(acc[0][2], w1.x, x0); ffma2(acc[0][3], w1.y, x0);
        ffma2(acc[1][0], w0.x, x1); ffma2(acc[1][1], w0.y, x1);
        ffma2(acc[1][2], w1.x, x1); ffma2(acc[1][3], w1.y, x1);
        ffma2(acc[2][0], w0.x, x2); ffma2(acc[2][1], w0.y, x2);
        ffma2(acc[2][2], w1.x, x2); ffma2(acc[2][3], w1.y, x2);
        ffma2(acc[3][0], w0.x, x3); ffma2(acc[3][1], w0.y, x3);
        ffma2(acc[3][2], w1.x, x3); ffma2(acc[3][3], w1.y, x3);
    }
    float4 bA = __ldg((const float4*)(bias + ocg * 8));
    float4 bB = __ldg((const float4*)(bias + ocg * 8 + 4));
#pragma unroll
    for (int p = 0; p < 4; p++) {
        float r = rs[px4 * 4 + p];
        float2 f0 = unpack2(acc[p][0]), f1 = unpack2(acc[p][1]);
        float2 f2 = unpack2(acc[p][2]), f3 = unpack2(acc[p][3]);
        float4 oA = make_float4(f0.x * r + bA.x, f0.y * r + bA.y,
                                f1.x * r + bA.z, f1.y * r + bA.w);
        float4 oB = make_float4(f2.x * r + bB.x, f2.y * r + bB.y,
                                f3.x * r + bB.z, f3.y * r + bB.w);
        float4* op = (float4*)(outp + (p0 + px4 * 4 + p) * 128 + ocg * 8);
        op[0] = oA; op[1] = oB;
    }
}

// ---------------------------------------------------------------------------
// Attention. 1 CTA per 4x4 query block (grid 1024), 128 threads.
// k-window + q-tile staged in smem with per-row column rotation.
__global__ __launch_bounds__(128, 4) void attn_kernel(float* __restrict__ outp) {
    extern __shared__ __align__(16) float asm_[];
    float* ks = asm_;                // 49 rows x 132 (33 float4/row, rotated)
    float* qs = ks + 49 * 132;       // 16 rows x 132
    float* lg = qs + 16 * 132;       // [h][q][52] logits -> probs in place
    float* amT = lg + 4 * 16 * 52;   // [49][16] head-mean transposed
    int tid = threadIdx.x;
    int iq = blockIdx.x >> 5, jq = blockIdx.x & 31;
    int sy = iq - 3; sy = sy < 0 ? 0 : (sy > 25 ? 25 : sy);
    int sx = jq - 3; sx = sx < 0 ? 0 : (sx > 25 ? 25 : sx);
    int base = sy * 32 + sx;

    {
        float4* ks4 = (float4*)ks;
        float4* qs4 = (float4*)qs;
        const float4* kf4 = (const float4*)g_kf;
        const float4* qf4 = (const float4*)g_qf;
        for (int i = tid; i < 49 * 32; i += 128) {
            int kk = i >> 5, c4 = i & 31;
            int m = kk / 7, n = kk - m * 7;
            ks4[kk * 33 + ((c4 + (kk >> 1)) & 31)] = kf4[(base + m * 32 + n) * 32 + c4];
        }
        for (int i = tid; i < 16 * 32; i += 128) {
            int r = i >> 5, c4 = i & 31;
            int y = iq * 4 + (r >> 2), xx = jq * 4 + (r & 3);
            qs4[r * 33 + ((c4 + (r >> 1)) & 31)] = qf4[(y * 128 + xx) * 32 + c4];
        }
    }
    __syncthreads();

    // Phase 1: logits. thread = (head, q-pair, key-quarter).
    {
        int h = tid >> 5, lane = tid & 31;
        int qh = lane >> 2, kq = lane & 3;
        ull qr[2][16];
#pragma unroll
        for (int t = 0; t < 2; t++) {
            int qi = qh * 2 + t;
            const ulonglong2* qrow = (const ulonglong2*)((const float4*)qs + qi * 33);
            int rot = qi >> 1;
#pragma unroll
            for (int seg = 0; seg < 8; seg++) {
                ulonglong2 v = qrow[(h * 8 + seg + rot) & 31];
                qr[t][2 * seg] = v.x; qr[t][2 * seg + 1] = v.y;
            }
        }
        for (int j = 0; j < 13; j++) {
            if (j == 12 && kq != 3) break;
            int kk = kq * 12 + j;
            const ulonglong2* krow = (const ulonglong2*)((const float4*)ks + kk * 33);
            int rot = kk >> 1;
            ull kr[16];
#pragma unroll
            for (int seg = 0; seg < 8; seg++) {
                ulonglong2 v = krow[(h * 8 + seg + rot) & 31];
                kr[2 * seg] = v.x; kr[2 * seg + 1] = v.y;
            }
#pragma unroll
            for (int t = 0; t < 2; t++) {
                ull a = 0ULL;
#pragma unroll
                for (int u = 0; u < 16; u++) ffma2(a, qr[t][u], kr[u]);
                float2 f = unpack2(a);
                lg[h * 832 + (qh * 2 + t) * 52 + kk] = (f.x + f.y) * 0.17677669529663687f;
            }
        }
    }
    __syncthreads();

    if (tid < 64) {
        int q = tid & 15, h = tid >> 4;
        float* row = lg + h * 832 + q * 52;
        float mx = -1e30f;
#pragma unroll
        for (int kk = 0; kk < 49; kk++) mx = fmaxf(mx, row[kk]);
        float sum = 0.f;
#pragma unroll
        for (int kk = 0; kk < 49; kk++) { float e = __expf(row[kk] - mx); row[kk] = e; sum += e; }
        float inv = 1.f / sum;
#pragma unroll
        for (int kk = 0; kk < 49; kk++) row[kk] *= inv;
    }
    __syncthreads();

    for (int i = tid; i < 784; i += 128) {
        int q = i / 49, kk = i - q * 49;
        amT[kk * 16 + q] = 0.25f * (lg[q * 52 + kk] + lg[832 + q * 52 + kk] +
                                    lg[1664 + q * 52 + kk] + lg[2496 + q * 52 + kk]);
    }
    __syncthreads();

    {
        int qy = tid >> 5, cb = tid & 31;
        ull acc[4][2];
#pragma unroll
        for (int j = 0; j < 4; j++) { acc[j][0] = 0ULL; acc[j][1] = 0ULL; }
#pragma unroll
        for (int kk = 0; kk < 49; kk++) {
            int m = kk / 7, n = kk - m * 7;
            const float* vp = g_vt + (base + m * 32 + n) * 128 + cb;
            const ull* ap = (const ull*)(amT + kk * 16 + qy * 4);
            ull a01 = ap[0], a23 = ap[1];
#pragma unroll
            for (int j = 0; j < 4; j++) {
                ull vv = pack2(__ldg(vp + 32 * j));
                ffma2(acc[j][0], a01, vv);
                ffma2(acc[j][1], a23, vv);
            }
        }
        int y = iq * 4 + qy;
#pragma unroll
        for (int j = 0; j < 4; j++) {
            int c = cb + 32 * j;
            float2 r01 = unpack2(acc[j][0]);
            float2 r23 = unpack2(acc[j][1]);
            float4* op = (float4*)(outp + c * 16384 + y * 128 + jq * 4);
            op[0] = make_float4(r01.x, r01.y, r23.x, r23.y);
        }
    }
}

// ---------------------------------------------------------------------------
extern "C" void kernel_launch(void* const* d_in, const int* in_sizes, int n_in,
                              void* d_out, int out_size) {
    (void)in_sizes; (void)n_in; (void)out_size;
    const float* q  = (const float*)d_in[0];
    const float* k  = (const float*)d_in[1];
    const float* v  = (const float*)d_in[2];
    const float* cw = (const float*)d_in[3];
    const float* nq = (const float*)d_in[4];
    const float* nk = (const float*)d_in[5];
    const float* qw = (const float*)d_in[6];
    const float* qb = (const float*)d_in[7];
    const float* kw = (const float*)d_in[8];
    const float* kb = (const float*)d_in[9];
    float* out = (float*)d_out;

    void *qc_p, *qf_p, *kf_p, *wq_p, *wk_p;
    cudaGetSymbolAddress(&qc_p, g_qc);
    cudaGetSymbolAddress(&qf_p, g_qf);
    cudaGetSymbolAddress(&kf_p, g_kf);
    cudaGetSymbolAddress(&wq_p, g_Wq);
    cudaGetSymbolAddress(&wk_p, g_Wk);

    const int proj_smem = (128 * 128 + 128 * 64 + 4 * 64 + 64) * 4;  // 98560 B
    cudaFuncSetAttribute(proj_kernel, cudaFuncAttributeMaxDynamicSharedMemorySize, proj_smem);

    fold_kernel<<<64, 256>>>(qw, nq, kw, nk);
    vtrans_kernel<<<512, 256>>>(v);
    proj_kernel<<<16, 256, proj_smem>>>(k, (const float*)wk_p, kb, (float*)kf_p, 1024);
    conv3_kernel<<<dim3(4, 8, 8), 256>>>(q, cw);
    proj_kernel<<<256, 256, proj_smem>>>((const float*)qc_p, (const float*)wq_p, qb,
                                         (float*)qf_p, 16384);

    const int attn_smem = (49 * 132 + 16 * 132 + 4 * 16 * 52 + 49 * 16) * 4;  // 50768 B
    cudaFuncSetAttribute(attn_kernel, cudaFuncAttributeMaxDynamicSharedMemorySize, attn_smem);
    attn_kernel<<<1024, 128, attn_smem>>>(out);
}

// round 8
// speedup vs baseline: 3.0403x; 1.7822x over previous
#include <cuda_runtime.h>
#include <cuda_bf16.h>

// ---------------------------------------------------------------------------
// NATTEN cross-attention block.
// conv3x3(q) [bf16-split tensor-core implicit GEMM] -> rmsnorm+qproj ->
// rmsnorm+kproj(k) -> attention.
// Attention: upsample-by-4 + dilation-4 NATTEN == each 4x4 query block attends
// to a 7x7 window of the ORIGINAL 32x32 k/v grid, start clamp(iq-3, 0, 25).
// ---------------------------------------------------------------------------

#define EPSF 1.1920928955078125e-7f
typedef unsigned long long ull;
typedef unsigned int u32;

__device__ float g_qc[128 * 128 * 128];            // conv output, NCHW
__device__ float g_qf[128 * 128 * 128];            // q final, pixel-major
__device__ float g_kf[32 * 32 * 128];              // k final, pixel-major
__device__ float g_vt[32 * 32 * 128];              // v transposed, pixel-major
__device__ float g_Wq[128 * 128];                  // folded qproj [c][o]
__device__ float g_Wk[128 * 128];                  // folded kproj [c][o]
__device__ __nv_bfloat16 g_xh[130 * 130 * 128];    // conv input hi, padded pixel-major
__device__ __nv_bfloat16 g_xl[130 * 130 * 128];    // conv input lo
__device__ __nv_bfloat16 g_wh[9 * 128 * 128];      // conv weights hi [tap][oc][ic]
__device__ __nv_bfloat16 g_wl[9 * 128 * 128];      // conv weights lo

__device__ __forceinline__ ull pack2(float v) {
    ull r; asm("mov.b64 %0, {%1, %1};" : "=l"(r) : "f"(v)); return r;
}
__device__ __forceinline__ void ffma2(ull& d, ull a, ull b) {
    asm("fma.rn.f32x2 %0, %1, %2, %0;" : "+l"(d) : "l"(a), "l"(b));
}
__device__ __forceinline__ float2 unpack2(ull v) {
    float2 f; asm("mov.b64 {%0, %1}, %2;" : "=f"(f.x), "=f"(f.y) : "l"(v)); return f;
}
__device__ __forceinline__ void mma16816(float* c, const u32* a, const u32* b) {
    asm volatile(
        "mma.sync.aligned.m16n8k16.row.col.f32.bf16.bf16.f32 "
        "{%0,%1,%2,%3}, {%4,%5,%6,%7}, {%8,%9}, {%0,%1,%2,%3};"
        : "+f"(c[0]), "+f"(c[1]), "+f"(c[2]), "+f"(c[3])
        : "r"(a[0]), "r"(a[1]), "r"(a[2]), "r"(a[3]), "r"(b[0]), "r"(b[1]));
}
__device__ __forceinline__ unsigned short bits16(__nv_bfloat16 h) {
    return *(unsigned short*)&h;
}

// ---------------------------------------------------------------------------
__global__ void fold_kernel(const float* __restrict__ qw, const float* __restrict__ nq,
                            const float* __restrict__ kw, const float* __restrict__ nk) {
    int i = blockIdx.x * 256 + threadIdx.x;
    if (i < 128 * 128) {
        int c = i >> 7, o = i & 127;
        g_Wq[i] = qw[o * 128 + c] * nq[c];
        g_Wk[i] = kw[o * 128 + c] * nk[c];
    }
}

__global__ void vtrans_kernel(const float* __restrict__ v) {
    int i = blockIdx.x * 256 + threadIdx.x;
    if (i < 32 * 32 * 128) {
        int c = i >> 10, p = i & 1023;
        g_vt[p * 128 + c] = v[i];
    }
}

// conv weights: [oc][ic][3][3] fp32 -> hi/lo bf16 [tap][oc][ic]
__global__ void wprep_kernel(const float* __restrict__ w) {
    int i = blockIdx.x * 256 + threadIdx.x;
    if (i < 9 * 128 * 128) {
        int tap = i >> 14, oc = (i >> 7) & 127, ic = i & 127;
        float v = w[(oc * 128 + ic) * 9 + tap];
        __nv_bfloat16 hi = __float2bfloat16_rn(v);
        __nv_bfloat16 lo = __float2bfloat16_rn(v - __bfloat162float(hi));
        g_wh[i] = hi;
        g_wl[i] = lo;
    }
}

// conv input: NCHW fp32 -> padded pixel-major bf16 hi/lo. CTA: 64 px x 128 c.
__global__ __launch_bounds__(256) void qprep_kernel(const float* __restrict__ x) {
    __shared__ float s[128 * 67];   // [c][px], stride 67
    int tid = threadIdx.x;
    int p0 = blockIdx.x * 64;
    const float4* x4 = (const float4*)x;
#pragma unroll
    for (int j = 0; j < 8; j++) {
        int idx = tid + 256 * j;
        int c = idx >> 4, seg = idx & 15;
        float4 v = x4[c * 4096 + (p0 >> 2) + seg];
        s[c * 67 + seg * 4 + 0] = v.x;
        s[c * 67 + seg * 4 + 1] = v.y;
        s[c * 67 + seg * 4 + 2] = v.z;
        s[c * 67 + seg * 4 + 3] = v.w;
    }
    __syncthreads();
#pragma unroll
    for (int j = 0; j < 8; j++) {
        int idx = tid + 256 * j;        // 2048 = 64px * 32 cquads
        int cq = idx & 31, pix = idx >> 5;
        int p = p0 + pix;
        int py = p >> 7, px = p & 127;
        long long ob = ((long long)((py + 1) * 130 + (px + 1))) * 128 + cq * 4;
        uint2 uh, ul;
        float v0 = s[(cq * 4 + 0) * 67 + pix];
        float v1 = s[(cq * 4 + 1) * 67 + pix];
        float v2 = s[(cq * 4 + 2) * 67 + pix];
        float v3 = s[(cq * 4 + 3) * 67 + pix];
        __nv_bfloat16 h0 = __float2bfloat16_rn(v0), h1 = __float2bfloat16_rn(v1);
        __nv_bfloat16 h2 = __float2bfloat16_rn(v2), h3 = __float2bfloat16_rn(v3);
        __nv_bfloat16 l0 = __float2bfloat16_rn(v0 - __bfloat162float(h0));
        __nv_bfloat16 l1 = __float2bfloat16_rn(v1 - __bfloat162float(h1));
        __nv_bfloat16 l2 = __float2bfloat16_rn(v2 - __bfloat162float(h2));
        __nv_bfloat16 l3 = __float2bfloat16_rn(v3 - __bfloat162float(h3));
        uh.x = (u32)bits16(h0) | ((u32)bits16(h1) << 16);
        uh.y = (u32)bits16(h2) | ((u32)bits16(h3) << 16);
        ul.x = (u32)bits16(l0) | ((u32)bits16(l1) << 16);
        ul.y = (u32)bits16(l2) | ((u32)bits16(l3) << 16);
        *(uint2*)(g_xh + ob) = uh;
        *(uint2*)(g_xl + ob) = ul;
    }
}

// zero the 1-pixel border of g_xh/g_xl. 516 border pixels * 16 uint4 each.
__global__ void border_kernel() {
    int idx = blockIdx.x * 256 + threadIdx.x;
    if (idx < 516 * 16) {
        int b = idx >> 4, seg = idx & 15;
        int row, col;
        if (b < 260) { row = (b / 130) * 129; col = b % 130; }
        else { int b2 = b - 260; col = (b2 < 128) ? 0 : 129; row = 1 + (b2 & 127); }
        long long o = ((long long)(row * 130 + col)) * 128 + seg * 8;
        uint4 z = make_uint4(0, 0, 0, 0);
        *(uint4*)(g_xh + o) = z;
        *(uint4*)(g_xl + o) = z;
    }
}

// ---------------------------------------------------------------------------
// Implicit-GEMM 3x3 conv via bf16-split mma.sync. Grid 128 CTAs, 256 threads.
// CTA tile: 8 rows x 16 cols pixels (M=128) x 128 oc. Warp = 64 px x 32 oc.
// K = 128 ic per tap, 9 taps, 3 split-products (hh, hl, lh).
__global__ __launch_bounds__(256, 1) void convmma_kernel() {
    extern __shared__ __align__(16) __nv_bfloat16 sm[];
    __nv_bfloat16* sAh = sm;                 // [180 px][136]
    __nv_bfloat16* sAl = sm + 24480;
    __nv_bfloat16* sBh = sm + 48960;         // [128 oc][136]
    __nv_bfloat16* sBl = sm + 66368;
    float* sC = (float*)sm;                  // epilogue [128][133]

    int tile = blockIdx.x;
    int py0 = (tile >> 3) * 8;
    int px0 = (tile & 7) * 16;
    int tid = threadIdx.x;
    int wid = tid >> 5, lane = tid & 31;
    int g = lane >> 2, t = lane & 3;
    int wm = wid >> 2, wn = wid & 3;
    int m0w = wm * 64, n0w = wn * 32;

    // Stage A patch (both splits)
    {
        uint4* dAh = (uint4*)sAh;
        uint4* dAl = (uint4*)sAl;
        const uint4* gh = (const uint4*)g_xh;
        const uint4* gl = (const uint4*)g_xl;
        for (int idx = tid; idx < 2880; idx += 256) {
            int pix = idx >> 4, seg = idx & 15;
            int r = pix / 18, cc = pix - r * 18;
            int gi = ((py0 + r) * 130 + px0 + cc) * 16 + seg;
            int si = pix * 17 + seg;
            dAh[si] = gh[gi];
            dAl[si] = gl[gi];
        }
    }

    float acc[4][4][4];
#pragma unroll
    for (int a = 0; a < 4; a++)
#pragma unroll
        for (int b = 0; b < 4; b++)
#pragma unroll
            for (int c = 0; c < 4; c++) acc[a][b][c] = 0.f;

    // per-lane A pixel bases (patch pixel idx) for frag rows g and g+8
    int pb0[4], pb1[4];
#pragma unroll
    for (int mi = 0; mi < 4; mi++) {
        int r = wm * 4 + mi;
        pb0[mi] = r * 18 + g;
        pb1[mi] = r * 18 + g + 8;
    }

    for (int tap = 0; tap < 9; tap++) {
        int dy = tap / 3, dx = tap - dy * 3;
        __syncthreads();   // previous B fully consumed / A staged
        {
            uint4* dBh = (uint4*)sBh;
            uint4* dBl = (uint4*)sBl;
            const uint4* gwh = (const uint4*)g_wh + tap * 2048;
            const uint4* gwl = (const uint4*)g_wl + tap * 2048;
            for (int idx = tid; idx < 2048; idx += 256) {
                int oc = idx >> 4, seg = idx & 15;
                int si = oc * 17 + seg;
                dBh[si] = gwh[idx];
                dBl[si] = gwl[idx];
            }
        }
        __syncthreads();
        int toff = (dy * 18 + dx) * 136 + 2 * t;

#pragma unroll
        for (int ks = 0; ks < 8; ks++) {
            int kofs = ks * 16;
            u32 bh[4][2], bl[4][2];
#pragma unroll
            for (int ni = 0; ni < 4; ni++) {
                int n = n0w + ni * 8 + g;
                const u32* ph = (const u32*)(sBh + n * 136 + kofs + 2 * t);
                const u32* pl = (const u32*)(sBl + n * 136 + kofs + 2 * t);
                bh[ni][0] = ph[0]; bh[ni][1] = ph[4];
                bl[ni][0] = pl[0]; bl[ni][1] = pl[4];
            }
#pragma unroll
            for (int mi = 0; mi < 4; mi++) {
                u32 ah[4], al[4];
                const u32* p0h = (const u32*)(sAh + pb0[mi] * 136 + toff + kofs);
                const u32* p1h = (const u32*)(sAh + pb1[mi] * 136 + toff + kofs);
                const u32* p0l = (const u32*)(sAl + pb0[mi] * 136 + toff + kofs);
                const u32* p1l = (const u32*)(sAl + pb1[mi] * 136 + toff + kofs);
                ah[0] = p0h[0]; ah[1] = p1h[0]; ah[2] = p0h[4]; ah[3] = p1h[4];
                al[0] = p0l[0]; al[1] = p1l[0]; al[2] = p0l[4]; al[3] = p1l[4];
#pragma unroll
                for (int ni = 0; ni < 4; ni++) {
                    mma16816(acc[mi][ni], ah, bh[ni]);   // xh * wh
                    mma16816(acc[mi][ni], ah, bl[ni]);   // xh * wl
                    mma16816(acc[mi][ni], al, bh[ni]);   // xl * wh
                }
            }
        }
    }

    __syncthreads();   // A/B dead; reuse smem for C
#pragma unroll
    for (int mi = 0; mi < 4; mi++) {
        int mA = m0w + mi * 16 + g;
        int mB = mA + 8;
#pragma unroll
        for (int ni = 0; ni < 4; ni++) {
            int n = n0w + ni * 8 + 2 * t;
            sC[mA * 133 + n] = acc[mi][ni][0];
            sC[mA * 133 + n + 1] = acc[mi][ni][1];
            sC[mB * 133 + n] = acc[mi][ni][2];
            sC[mB * 133 + n + 1] = acc[mi][ni][3];
        }
    }
    __syncthreads();
    // FIX (R6 crash): 128 oc x 32 m-quads = 4096 iterations (was 16384 ->
    // oc up to 511 -> OOB store into g_qc).
    float4* qc4 = (float4*)g_qc;
    for (int idx = tid; idx < 4096; idx += 256) {
        int oc = idx >> 5, f4 = idx & 31;
        int m = f4 * 4;
        float4 v = make_float4(sC[m * 133 + oc], sC[(m + 1) * 133 + oc],
                               sC[(m + 2) * 133 + oc], sC[(m + 3) * 133 + oc]);
        int r = m >> 4, c = m & 15;
        qc4[(oc * 16384 + (py0 + r) * 128 + px0 + c) >> 2] = v;
    }
}

// ---------------------------------------------------------------------------
// Fused RMSNorm + 1x1 projection GEMM, weights staged in smem.
__global__ __launch_bounds__(256) void proj_kernel(const float* __restrict__ xin,
                                                   const float* __restrict__ Wt,
                                                   const float* __restrict__ bias,
                                                   float* __restrict__ outp, int HW) {
    extern __shared__ __align__(16) float psm[];
    float* sW = psm;                // [128][128]
    float* xs = sW + 128 * 128;     // [128][64]
    float* red = xs + 128 * 64;
    float* rs = red + 4 * 64;
    int tid = threadIdx.x;
    int p0 = blockIdx.x * 64;

    float4* sW4 = (float4*)sW;
    const float4* Wt4 = (const float4*)Wt;
#pragma unroll
    for (int j = 0; j < 16; j++) sW4[tid + 256 * j] = Wt4[tid + 256 * j];

    float4* xs4 = (float4*)xs;
    const float4* xin4 = (const float4*)xin;
#pragma unroll
    for (int j = 0; j < 8; j++) {
        int idx = tid + 256 * j;
        int c = idx >> 4, seg = idx & 15;
        xs4[idx] = xin4[c * (HW >> 2) + (p0 >> 2) + seg];
    }
    __syncthreads();
    {
        int px = tid & 63, gg = tid >> 6;
        float s = 0.f;
#pragma unroll
        for (int j = 0; j < 32; j++) {
            float v = xs[(gg * 32 + j) * 64 + px];
            s += v * v;
        }
        red[gg * 64 + px] = s;
    }
    __syncthreads();
    if (tid < 64)
        rs[tid] = rsqrtf((red[tid] + red[64 + tid] + red[128 + tid] + red[192 + tid]) *
                         (1.f / 128.f) + EPSF);
    __syncthreads();

    int px4 = tid & 15;
    int ocg = tid >> 4;
    ull acc[4][4];
#pragma unroll
    for (int i = 0; i < 4; i++)
#pragma unroll
        for (int j = 0; j < 4; j++) acc[i][j] = 0ULL;

#pragma unroll 4
    for (int c = 0; c < 128; c++) {
        float4 xa = xs4[c * 16 + px4];
        ull x0 = pack2(xa.x), x1 = pack2(xa.y), x2 = pack2(xa.z), x3 = pack2(xa.w);
        const ulonglong2* wp = (const ulonglong2*)(sW + c * 128 + ocg * 8);
        ulonglong2 w0 = wp[0], w1 = wp[1];
        ffma2(acc[0][0], w0.x, x0); ffma2(acc[0][1], w0.y, x0);
        ffma2(acc[0][2], w1.x, x0); ffma2(acc[0][3], w1.y, x0);
        ffma2(acc[1][0], w0.x, x1); ffma2(acc[1][1], w0.y, x1);
        ffma2(acc[1][2], w1.x, x1); ffma2(acc[1][3], w1.y, x1);
        ffma2(acc[2][0], w0.x, x2); ffma2(acc[2][1], w0.y, x2);
        ffma2(acc[2][2], w1.x, x2); ffma2(acc[2][3], w1.y, x2);
        ffma2(acc[3][0], w0.x, x3); ffma2(acc[3][1], w0.y, x3);
        ffma2(acc[3][2], w1.x, x3); ffma2(acc[3][3], w1.y, x3);
    }
    float4 bA = __ldg((const float4*)(bias + ocg * 8));
    float4 bB = __ldg((const float4*)(bias + ocg * 8 + 4));
#pragma unroll
    for (int p = 0; p < 4; p++) {
        float r = rs[px4 * 4 + p];
        float2 f0 = unpack2(acc[p][0]), f1 = unpack2(acc[p][1]);
        float2 f2 = unpack2(acc[p][2]), f3 = unpack2(acc[p][3]);
        float4 oA = make_float4(f0.x * r + bA.x, f0.y * r + bA.y,
                                f1.x * r + bA.z, f1.y * r + bA.w);
        float4 oB = make_float4(f2.x * r + bB.x, f2.y * r + bB.y,
                                f3.x * r + bB.z, f3.y * r + bB.w);
        float4* op = (float4*)(outp + (p0 + px4 * 4 + p) * 128 + ocg * 8);
        op[0] = oA; op[1] = oB;
    }
}

// ---------------------------------------------------------------------------
// Attention. 1 CTA per 4x4 query block (grid 1024), 128 threads.
__global__ __launch_bounds__(128, 4) void attn_kernel(float* __restrict__ outp) {
    extern __shared__ __align__(16) float asm_[];
    float* ks = asm_;
    float* qs = ks + 49 * 132;
    float* lg = qs + 16 * 132;
    float* amT = lg + 4 * 16 * 52;
    int tid = threadIdx.x;
    int iq = blockIdx.x >> 5, jq = blockIdx.x & 31;
    int sy = iq - 3; sy = sy < 0 ? 0 : (sy > 25 ? 25 : sy);
    int sx = jq - 3; sx = sx < 0 ? 0 : (sx > 25 ? 25 : sx);
    int base = sy * 32 + sx;

    {
        float4* ks4 = (float4*)ks;
        float4* qs4 = (float4*)qs;
        const float4* kf4 = (const float4*)g_kf;
        const float4* qf4 = (const float4*)g_qf;
        for (int i = tid; i < 49 * 32; i += 128) {
            int kk = i >> 5, c4 = i & 31;
            int m = kk / 7, n = kk - m * 7;
            ks4[kk * 33 + ((c4 + (kk >> 1)) & 31)] = kf4[(base + m * 32 + n) * 32 + c4];
        }
        for (int i = tid; i < 16 * 32; i += 128) {
            int r = i >> 5, c4 = i & 31;
            int y = iq * 4 + (r >> 2), xx = jq * 4 + (r & 3);
            qs4[r * 33 + ((c4 + (r >> 1)) & 31)] = qf4[(y * 128 + xx) * 32 + c4];
        }
    }
    __syncthreads();

    {
        int h = tid >> 5, lane = tid & 31;
        int qh = lane >> 2, kq = lane & 3;
        ull qr[2][16];
#pragma unroll
        for (int tt = 0; tt < 2; tt++) {
            int qi = qh * 2 + tt;
            const ulonglong2* qrow = (const ulonglong2*)((const float4*)qs + qi * 33);
            int rot = qi >> 1;
#pragma unroll
            for (int seg = 0; seg < 8; seg++) {
                ulonglong2 v = qrow[(h * 8 + seg + rot) & 31];
                qr[tt][2 * seg] = v.x; qr[tt][2 * seg + 1] = v.y;
            }
        }
        for (int j = 0; j < 13; j++) {
            if (j == 12 && kq != 3) break;
            int kk = kq * 12 + j;
            const ulonglong2* krow = (const ulonglong2*)((const float4*)ks + kk * 33);
            int rot = kk >> 1;
            ull kr[16];
#pragma unroll
            for (int seg = 0; seg < 8; seg++) {
                ulonglong2 v = krow[(h * 8 + seg + rot) & 31];
                kr[2 * seg] = v.x; kr[2 * seg + 1] = v.y;
            }
#pragma unroll
            for (int tt = 0; tt < 2; tt++) {
                ull a = 0ULL;
#pragma unroll
                for (int u = 0; u < 16; u++) ffma2(a, qr[tt][u], kr[u]);
                float2 f = unpack2(a);
                lg[h * 832 + (qh * 2 + tt) * 52 + kk] = (f.x + f.y) * 0.17677669529663687f;
            }
        }
    }
    __syncthreads();

    if (tid < 64) {
        int q = tid & 15, h = tid >> 4;
        float* row = lg + h * 832 + q * 52;
        float mx = -1e30f;
#pragma unroll
        for (int kk = 0; kk < 49; kk++) mx = fmaxf(mx, row[kk]);
        float sum = 0.f;
#pragma unroll
        for (int kk = 0; kk < 49; kk++) { float e = __expf(row[kk] - mx); row[kk] = e; sum += e; }
        float inv = 1.f / sum;
#pragma unroll
        for (int kk = 0; kk < 49; kk++) row[kk] *= inv;
    }
    __syncthreads();

    for (int i = tid; i < 784; i += 128) {
        int q = i / 49, kk = i - q * 49;
        amT[kk * 16 + q] = 0.25f * (lg[q * 52 + kk] + lg[832 + q * 52 + kk] +
                                    lg[1664 + q * 52 + kk] + lg[2496 + q * 52 + kk]);
    }
    __syncthreads();

    {
        int qy = tid >> 5, cb = tid & 31;
        ull acc[4][2];
#pragma unroll
        for (int j = 0; j < 4; j++) { acc[j][0] = 0ULL; acc[j][1] = 0ULL; }
#pragma unroll
        for (int kk = 0; kk < 49; kk++) {
            int m = kk / 7, n = kk - m * 7;
            const float* vp = g_vt + (base + m * 32 + n) * 128 + cb;
            const ull* ap = (const ull*)(amT + kk * 16 + qy * 4);
            ull a01 = ap[0], a23 = ap[1];
#pragma unroll
            for (int j = 0; j < 4; j++) {
                ull vv = pack2(__ldg(vp + 32 * j));
                ffma2(acc[j][0], a01, vv);
                ffma2(acc[j][1], a23, vv);
            }
        }
        int y = iq * 4 + qy;
#pragma unroll
        for (int j = 0; j < 4; j++) {
            int c = cb + 32 * j;
            float2 r01 = unpack2(acc[j][0]);
            float2 r23 = unpack2(acc[j][1]);
            float4* op = (float4*)(outp + c * 16384 + y * 128 + jq * 4);
            op[0] = make_float4(r01.x, r01.y, r23.x, r23.y);
        }
    }
}

// ---------------------------------------------------------------------------
extern "C" void kernel_launch(void* const* d_in, const int* in_sizes, int n_in,
                              void* d_out, int out_size) {
    (void)in_sizes; (void)n_in; (void)out_size;
    const float* q  = (const float*)d_in[0];
    const float* k  = (const float*)d_in[1];
    const float* v  = (const float*)d_in[2];
    const float* cw = (const float*)d_in[3];
    const float* nq = (const float*)d_in[4];
    const float* nk = (const float*)d_in[5];
    const float* qw = (const float*)d_in[6];
    const float* qb = (const float*)d_in[7];
    const float* kw = (const float*)d_in[8];
    const float* kb = (const float*)d_in[9];
    float* out = (float*)d_out;

    void *qc_p, *qf_p, *kf_p, *wq_p, *wk_p;
    cudaGetSymbolAddress(&qc_p, g_qc);
    cudaGetSymbolAddress(&qf_p, g_qf);
    cudaGetSymbolAddress(&kf_p, g_kf);
    cudaGetSymbolAddress(&wq_p, g_Wq);
    cudaGetSymbolAddress(&wk_p, g_Wk);

    const int proj_smem = (128 * 128 + 128 * 64 + 4 * 64 + 64) * 4;
    cudaFuncSetAttribute(proj_kernel, cudaFuncAttributeMaxDynamicSharedMemorySize, proj_smem);
    const int conv_smem = 167552;
    cudaFuncSetAttribute(convmma_kernel, cudaFuncAttributeMaxDynamicSharedMemorySize, conv_smem);

    fold_kernel<<<64, 256>>>(qw, nq, kw, nk);
    vtrans_kernel<<<512, 256>>>(v);
    wprep_kernel<<<576, 256>>>(cw);
    qprep_kernel<<<256, 256>>>(q);
    border_kernel<<<33, 256>>>();
    proj_kernel<<<16, 256, proj_smem>>>(k, (const float*)wk_p, kb, (float*)kf_p, 1024);
    convmma_kernel<<<128, 256, conv_smem>>>();
    proj_kernel<<<256, 256, proj_smem>>>((const float*)qc_p, (const float*)wq_p, qb,
                                         (float*)qf_p, 16384);

    const int attn_smem = (49 * 132 + 16 * 132 + 4 * 16 * 52 + 49 * 16) * 4;
    cudaFuncSetAttribute(attn_kernel, cudaFuncAttributeMaxDynamicSharedMemorySize, attn_smem);
    attn_kernel<<<1024, 128, attn_smem>>>(out);
}